// round 9
// baseline (speedup 1.0000x reference)
#include <cuda_runtime.h>
#include <math.h>

#define NB_   512
#define MS_   8
#define T_    64
#define IN_   360
#define H_    230
#define H2_   460
#define H3_   690
#define OUT_  53
#define ENT_  8
#define B_    4096
#define M_    (B_ * T_)

typedef unsigned long long u64;

__device__ float g_xg[2][M_ * H3_];           // input projection (+b_ih)
__device__ float g_out_buf[M_ * H2_];         // concat(hf,hr), layout [t][b][h]
__device__ float g_h[2][2][B_ * H_];          // ping-pong hidden per dir
__device__ float g_score[M_];                 // word scores [t][b]
__device__ float g_wv[B_ * H2_];              // word vectors
__device__ float g_score2[B_];                // sentence scores

__device__ __forceinline__ u64 pack_dup(float b) {
    u64 r; asm("mov.b64 %0, {%1, %2};" : "=l"(r) : "f"(b), "f"(b)); return r;
}
__device__ __forceinline__ void fma2(u64& acc, u64 a, u64 b) {
    asm("fma.rn.f32x2 %0, %1, %2, %0;" : "+l"(acc) : "l"(a), "l"(b));
}
__device__ __forceinline__ float2 unpk(u64 v) {
    float lo, hi; asm("mov.b64 {%0, %1}, %2;" : "=f"(lo), "=f"(hi) : "l"(v));
    return make_float2(lo, hi);
}
__device__ __forceinline__ float sigm(float x) { return 1.0f / (1.0f + __expf(-x)); }

// ---------------- zero: d_out + hidden state --------------------------------
__global__ void zero_kernel(float* out, int n_out) {
    size_t i = (size_t)blockIdx.x * blockDim.x + threadIdx.x;
    if (i < (size_t)n_out) out[i] = 0.0f;
    float* p = &g_h[0][0][0];
    size_t tot = (size_t)2 * 2 * B_ * H_;
    for (size_t j = i; j < tot; j += (size_t)gridDim.x * blockDim.x) p[j] = 0.0f;
}

// ---------------- input projection: xg = x @ W_ih^T + b_ih ------------------
// M=262144, K=360, N=690. Tile 128x64, KT=8, 256 threads, 2-stage pipeline.
__global__ __launch_bounds__(256, 3) void input_proj_kernel(
    const float* __restrict__ bag,
    const float* __restrict__ Wf, const float* __restrict__ bf,
    const float* __restrict__ Wr, const float* __restrict__ br)
{
    const int dir = blockIdx.z;
    const float* __restrict__ W    = dir ? Wr : Wf;
    const float* __restrict__ bias = dir ? br : bf;
    float* __restrict__ xg = g_xg[dir];

    const int    n0 = blockIdx.x * 64;
    const size_t m0 = (size_t)blockIdx.y * 128;

    __shared__ float As[2][8][128];
    __shared__ float Bs[2][8][64];

    const int tid = threadIdx.x;
    const int tx = tid & 15, ty = tid >> 4;
    const int lrow = tid >> 1, lkk = (tid & 1) * 4;
    const int bn = tid >> 2,  bkk = (tid & 3) * 2;
    const bool bok = (n0 + bn) < H3_;

    const float* aptr = bag + ((m0 + lrow) * IN_ + lkk);
    const float* wptr = W + (size_t)(n0 + bn) * IN_ + bkk;

    u64 acc[4][4];
#pragma unroll
    for (int i = 0; i < 4; i++)
#pragma unroll
        for (int j = 0; j < 4; j++) acc[i][j] = 0ull;

    // preload stage 0
    {
        float2 a0 = *(const float2*)aptr;
        float2 a1 = *(const float2*)(aptr + 2);
        float2 w  = bok ? *(const float2*)wptr : make_float2(0.f, 0.f);
        As[0][lkk][lrow] = a0.x; As[0][lkk+1][lrow] = a0.y;
        As[0][lkk+2][lrow] = a1.x; As[0][lkk+3][lrow] = a1.y;
        Bs[0][bkk][bn] = w.x; Bs[0][bkk+1][bn] = w.y;
    }
    __syncthreads();

    const int NIT = IN_ / 8;                       // 45
    for (int it = 0; it < NIT; it++) {
        const int cur = it & 1;
        float2 p0, p1, pw;
        if (it + 1 < NIT) {
            const int k0n = (it + 1) * 8;
            p0 = *(const float2*)(aptr + k0n);
            p1 = *(const float2*)(aptr + k0n + 2);
            pw = bok ? *(const float2*)(wptr + k0n) : make_float2(0.f, 0.f);
        }
#pragma unroll
        for (int k = 0; k < 8; k++) {
            u64 a[4];
#pragma unroll
            for (int i = 0; i < 4; i++) a[i] = *(const u64*)&As[cur][k][ty * 8 + i * 2];
#pragma unroll
            for (int j = 0; j < 4; j++) {
                u64 bb = pack_dup(Bs[cur][k][j * 16 + tx]);
#pragma unroll
                for (int i = 0; i < 4; i++) fma2(acc[i][j], a[i], bb);
            }
        }
        if (it + 1 < NIT) {
            const int nx = cur ^ 1;
            As[nx][lkk][lrow] = p0.x; As[nx][lkk+1][lrow] = p0.y;
            As[nx][lkk+2][lrow] = p1.x; As[nx][lkk+3][lrow] = p1.y;
            Bs[nx][bkk][bn] = pw.x; Bs[nx][bkk+1][bn] = pw.y;
        }
        __syncthreads();
    }
#pragma unroll
    for (int j = 0; j < 4; j++) {
        int n = n0 + j * 16 + tx;
        if (n >= H3_) continue;
        float bi = bias[n];
#pragma unroll
        for (int i = 0; i < 4; i++) {
            float2 v = unpk(acc[i][j]);
            size_t m = m0 + ty * 8 + i * 2;
            xg[m * H3_ + n]       = v.x + bi;
            xg[(m + 1) * H3_ + n] = v.y + bi;
        }
    }
}

// ---------------- GRU step: hg = h @ W_hh^T, fused gates --------------------
// Per dir: M=4096, K=230. Block = 128 rows x (32 cols x 3 gates). 2-stage.
__global__ __launch_bounds__(256, 3) void gru_step_kernel(int s,
    const float* __restrict__ Whf, const float* __restrict__ bhf,
    const float* __restrict__ Whr, const float* __restrict__ bhr)
{
    const int dir  = blockIdx.z;
    const int tIdx = dir ? (T_ - 1 - s) : s;
    const float* __restrict__ W     = dir ? Whr : Whf;
    const float* __restrict__ bhh   = dir ? bhr : bhf;
    const float* __restrict__ hprev = g_h[dir][s & 1];
    float*       __restrict__ hnext = g_h[dir][(s + 1) & 1];
    const float* __restrict__ xg    = g_xg[dir];

    const int    c0 = blockIdx.x * 32;
    const size_t m0 = (size_t)blockIdx.y * 128;

    __shared__ float As[2][8][128];
    __shared__ float Bs[2][8][3][32];

    const int tid = threadIdx.x;
    const int tx = tid & 15, ty = tid >> 4;
    const int lrow = tid >> 1, lkk = (tid & 1) * 4;
    const int bg = tid >> 5, bc = tid & 31;        // for B loads (tid<96)
    const bool cok = (tid < 96) && ((c0 + bc) < H_);
    const float* wp = W + (size_t)(bg * H_ + c0 + bc) * H_;
    const float* ap = hprev + ((m0 + lrow) * H_ + lkk);

    u64 acc[4][6];
#pragma unroll
    for (int i = 0; i < 4; i++)
#pragma unroll
        for (int j = 0; j < 6; j++) acc[i][j] = 0ull;

    const int NIT = (H_ + 7) / 8;                  // 29 (last partial)

    // preload stage 0 (k0=0; no upper-edge risk at k<8)
    {
        float2 a0 = *(const float2*)ap;
        float2 a1 = *(const float2*)(ap + 2);
        As[0][lkk][lrow] = a0.x; As[0][lkk+1][lrow] = a0.y;
        As[0][lkk+2][lrow] = a1.x; As[0][lkk+3][lrow] = a1.y;
        if (tid < 96) {
#pragma unroll
            for (int kk = 0; kk < 8; kk += 2) {
                float2 w = cok ? *(const float2*)(wp + kk) : make_float2(0.f, 0.f);
                Bs[0][kk][bg][bc] = w.x; Bs[0][kk+1][bg][bc] = w.y;
            }
        }
    }
    __syncthreads();

    for (int it = 0; it < NIT; it++) {
        const int cur = it & 1;
        float2 p0 = make_float2(0.f, 0.f), p1 = make_float2(0.f, 0.f);
        float2 pw[4];
        if (it + 1 < NIT) {
            const int k0n = (it + 1) * 8;
            if (k0n + lkk     < H_) p0 = *(const float2*)(ap + k0n);
            if (k0n + lkk + 2 < H_) p1 = *(const float2*)(ap + k0n + 2);
            if (tid < 96) {
#pragma unroll
                for (int kk = 0; kk < 8; kk += 2)
                    pw[kk >> 1] = (cok && (k0n + kk < H_))
                                  ? *(const float2*)(wp + k0n + kk)
                                  : make_float2(0.f, 0.f);
            }
        }
#pragma unroll
        for (int k = 0; k < 8; k++) {
            u64 a[4];
#pragma unroll
            for (int i = 0; i < 4; i++) a[i] = *(const u64*)&As[cur][k][ty * 8 + i * 2];
#pragma unroll
            for (int g = 0; g < 3; g++) {
                float2 w2 = *(const float2*)&Bs[cur][k][g][tx * 2];
                u64 b0 = pack_dup(w2.x);
                u64 b1 = pack_dup(w2.y);
#pragma unroll
                for (int i = 0; i < 4; i++) fma2(acc[i][g * 2],     a[i], b0);
#pragma unroll
                for (int i = 0; i < 4; i++) fma2(acc[i][g * 2 + 1], a[i], b1);
            }
        }
        if (it + 1 < NIT) {
            const int nx = cur ^ 1;
            As[nx][lkk][lrow] = p0.x; As[nx][lkk+1][lrow] = p0.y;
            As[nx][lkk+2][lrow] = p1.x; As[nx][lkk+3][lrow] = p1.y;
            if (tid < 96) {
#pragma unroll
                for (int kk = 0; kk < 8; kk += 2) {
                    Bs[nx][kk][bg][bc] = pw[kk >> 1].x;
                    Bs[nx][kk+1][bg][bc] = pw[kk >> 1].y;
                }
            }
        }
        __syncthreads();
    }

    const int c = c0 + tx * 2;
    if (c >= H_) return;                           // H_ even: pair never straddles
    const float br0 = bhh[c],          br1 = bhh[c + 1];
    const float bz0 = bhh[H_ + c],     bz1 = bhh[H_ + c + 1];
    const float bn0 = bhh[2 * H_ + c], bn1 = bhh[2 * H_ + c + 1];

#pragma unroll
    for (int i = 0; i < 4; i++) {
        float2 vr0 = unpk(acc[i][0]), vr1 = unpk(acc[i][1]);
        float2 vz0 = unpk(acc[i][2]), vz1 = unpk(acc[i][3]);
        float2 vn0 = unpk(acc[i][4]), vn1 = unpk(acc[i][5]);
#pragma unroll
        for (int half = 0; half < 2; half++) {
            size_t b = m0 + ty * 8 + i * 2 + half;
            float ar0 = half ? vr0.y : vr0.x, ar1 = half ? vr1.y : vr1.x;
            float az0 = half ? vz0.y : vz0.x, az1 = half ? vz1.y : vz1.x;
            float an0 = half ? vn0.y : vn0.x, an1 = half ? vn1.y : vn1.x;

            size_t xbase = (b * T_ + (size_t)tIdx) * H3_;
            float2 axr = *(const float2*)&xg[xbase + c];
            float2 axz = *(const float2*)&xg[xbase + H_ + c];
            float2 axn = *(const float2*)&xg[xbase + 2 * H_ + c];
            float2 hp  = *(const float2*)&hprev[b * H_ + c];

            float r0 = sigm(axr.x + ar0 + br0);
            float r1 = sigm(axr.y + ar1 + br1);
            float z0 = sigm(axz.x + az0 + bz0);
            float z1 = sigm(axz.y + az1 + bz1);
            float nn0 = tanhf(axn.x + r0 * (an0 + bn0));
            float nn1 = tanhf(axn.y + r1 * (an1 + bn1));
            float h0 = (1.f - z0) * nn0 + z0 * hp.x;
            float h1 = (1.f - z1) * nn1 + z1 * hp.y;

            *(float2*)&hnext[b * H_ + c] = make_float2(h0, h1);
            *(float2*)&g_out_buf[((size_t)tIdx * B_ + b) * H2_ + (size_t)dir * H_ + c] =
                make_float2(h0, h1);
        }
    }
}

// ---------------- fused attention score: score[m] = sum_n tanh((A@W)[m,n]+b[n])*p[n]
// which=0: A=g_out_buf (rows=262144) -> g_score ; which=1: A=g_wv (4096) -> g_score2
__global__ __launch_bounds__(256, 3) void attn_score_kernel(int which,
    const float* __restrict__ W, const float* __restrict__ bias,
    const float* __restrict__ proj)
{
    const float* __restrict__ A = which ? g_wv : g_out_buf;
    float* __restrict__ score   = which ? g_score2 : g_score;

    const size_t m0 = (size_t)blockIdx.x * 128;

    __shared__ float As[2][8][128];
    __shared__ float Bs[2][8][64];
    __shared__ float red[128][16];

    const int tid = threadIdx.x;
    const int tx = tid & 15, ty = tid >> 4;
    const int lrow = tid >> 1, lkk = (tid & 1) * 4;
    const int bkq = tid >> 5,  bnn = (tid & 31) * 2;

    const float* ap = A + ((m0 + lrow) * H2_ + lkk);

    float sp[8];
#pragma unroll
    for (int i = 0; i < 8; i++) sp[i] = 0.0f;

    const int NIT = (H2_ + 7) / 8;                 // 58 (last partial)

    for (int n0 = 0; n0 < H2_; n0 += 64) {
        u64 acc[4][4];
#pragma unroll
        for (int i = 0; i < 4; i++)
#pragma unroll
            for (int j = 0; j < 4; j++) acc[i][j] = 0ull;

        const bool wok0 = (n0 + bnn) < H2_;
        const float* wpb = W + (size_t)bkq * H2_ + n0 + bnn;

        // preload stage 0 (k0=0 fully valid)
        {
            float2 a0 = *(const float2*)ap;
            float2 a1 = *(const float2*)(ap + 2);
            As[0][lkk][lrow] = a0.x; As[0][lkk+1][lrow] = a0.y;
            As[0][lkk+2][lrow] = a1.x; As[0][lkk+3][lrow] = a1.y;
            float2 w = wok0 ? *(const float2*)wpb : make_float2(0.f, 0.f);
            Bs[0][bkq][bnn] = w.x; Bs[0][bkq][bnn + 1] = w.y;
        }
        __syncthreads();

        for (int it = 0; it < NIT; it++) {
            const int cur = it & 1;
            float2 p0 = make_float2(0.f, 0.f), p1 = make_float2(0.f, 0.f), pw = make_float2(0.f, 0.f);
            if (it + 1 < NIT) {
                const int k0n = (it + 1) * 8;
                if (k0n + lkk     < H2_) p0 = *(const float2*)(ap + k0n);
                if (k0n + lkk + 2 < H2_) p1 = *(const float2*)(ap + k0n + 2);
                if (wok0 && (k0n + bkq) < H2_)
                    pw = *(const float2*)(wpb + (size_t)k0n * H2_);
            }
#pragma unroll
            for (int k = 0; k < 8; k++) {
                u64 a[4];
#pragma unroll
                for (int i = 0; i < 4; i++) a[i] = *(const u64*)&As[cur][k][ty * 8 + i * 2];
#pragma unroll
                for (int j = 0; j < 4; j++) {
                    u64 bb = pack_dup(Bs[cur][k][j * 16 + tx]);
#pragma unroll
                    for (int i = 0; i < 4; i++) fma2(acc[i][j], a[i], bb);
                }
            }
            if (it + 1 < NIT) {
                const int nx = cur ^ 1;
                As[nx][lkk][lrow] = p0.x; As[nx][lkk+1][lrow] = p0.y;
                As[nx][lkk+2][lrow] = p1.x; As[nx][lkk+3][lrow] = p1.y;
                Bs[nx][bkq][bnn] = pw.x; Bs[nx][bkq][bnn + 1] = pw.y;
            }
            __syncthreads();
        }
#pragma unroll
        for (int j = 0; j < 4; j++) {
            int n = n0 + j * 16 + tx;
            if (n >= H2_) continue;
            float bi = bias[n], pj = proj[n];
#pragma unroll
            for (int i = 0; i < 4; i++) {
                float2 v = unpk(acc[i][j]);
                sp[i * 2]     += tanhf(v.x + bi) * pj;
                sp[i * 2 + 1] += tanhf(v.y + bi) * pj;
            }
        }
        __syncthreads();
    }
#pragma unroll
    for (int i = 0; i < 8; i++) red[ty * 8 + i][tx] = sp[i];
    __syncthreads();
    if (tid < 128) {
        float s = 0.f;
#pragma unroll
        for (int j = 0; j < 16; j++) s += red[tid][j];
        score[m0 + tid] = s;
    }
}

// ---------------- word softmax over t + weighted sum ------------------------
__global__ void word_vec_kernel() {
    int b = blockIdx.x;
    __shared__ float sc[T_], al[T_];
    int tid = threadIdx.x;
    if (tid < T_) sc[tid] = g_score[(size_t)tid * B_ + b];
    __syncthreads();
    float mx = -1e30f;
    for (int t = 0; t < T_; t++) mx = fmaxf(mx, sc[t]);
    float sm = 0.f;
    for (int t = 0; t < T_; t++) sm += __expf(sc[t] - mx);
    if (tid < T_) al[tid] = __expf(sc[tid] - mx) / sm;
    __syncthreads();
    for (int h = tid; h < H2_; h += blockDim.x) {
        float acc = 0.f;
        for (int t = 0; t < T_; t++)
            acc += al[t] * g_out_buf[((size_t)t * B_ + b) * H2_ + h];
        g_wv[(size_t)b * H2_ + h] = acc;
    }
}

// ---------------- sentence softmax + sent_vec + FC + scatter ----------------
__global__ void sent_fc_scatter_kernel(const int* __restrict__ pairs,
                                       const float* __restrict__ fcW,
                                       const float* __restrict__ fcb,
                                       float* __restrict__ out)
{
    int nb = blockIdx.x;
    int tid = threadIdx.x;
    __shared__ float sv[H2_];

    float sc[MS_], mx = -1e30f;
#pragma unroll
    for (int s = 0; s < MS_; s++) { sc[s] = g_score2[nb * MS_ + s]; mx = fmaxf(mx, sc[s]); }
    float sm = 0.f;
#pragma unroll
    for (int s = 0; s < MS_; s++) sm += __expf(sc[s] - mx);
    float be[MS_];
#pragma unroll
    for (int s = 0; s < MS_; s++) be[s] = __expf(sc[s] - mx) / sm;

    for (int h = tid; h < H2_; h += blockDim.x) {
        float acc = 0.f;
#pragma unroll
        for (int s = 0; s < MS_; s++)
            acc += be[s] * g_wv[((size_t)(nb * MS_ + s)) * H2_ + h];
        sv[h] = acc;
    }
    __syncthreads();

    int d = pairs[nb * 3], e1 = pairs[nb * 3 + 1], e2 = pairs[nb * 3 + 2];
    size_t base = (((size_t)d * ENT_ + e1) * ENT_ + e2) * OUT_;
    for (int o = tid; o < OUT_; o += blockDim.x) {
        float acc = fcb[o];
        for (int k = 0; k < H2_; k++) acc += sv[k] * fcW[(size_t)o * H2_ + k];
        out[base + o] = acc;
    }
}

// ---------------- launch ----------------------------------------------------
extern "C" void kernel_launch(void* const* d_in, const int* in_sizes, int n_in,
                              void* d_out, int out_size) {
    const float* bag   = (const float*)d_in[0];
    const float* Wihf  = (const float*)d_in[1];
    const float* Whhf  = (const float*)d_in[2];
    const float* bihf  = (const float*)d_in[3];
    const float* bhhf  = (const float*)d_in[4];
    const float* Wihr  = (const float*)d_in[5];
    const float* Whhr  = (const float*)d_in[6];
    const float* bihr  = (const float*)d_in[7];
    const float* bhhr  = (const float*)d_in[8];
    const float* Wword = (const float*)d_in[9];
    const float* bword = (const float*)d_in[10];
    const float* pword = (const float*)d_in[11];
    const float* Wsent = (const float*)d_in[12];
    const float* bsent = (const float*)d_in[13];
    const float* psent = (const float*)d_in[14];
    const float* fcW   = (const float*)d_in[15];
    const float* fcb   = (const float*)d_in[16];
    const int*   pairs = (const int*)d_in[17];
    float* out = (float*)d_out;

    zero_kernel<<<14720, 256>>>(out, out_size);
    input_proj_kernel<<<dim3(11, 2048, 2), 256>>>(bag, Wihf, bihf, Wihr, bihr);
    for (int s = 0; s < T_; s++)
        gru_step_kernel<<<dim3(8, 32, 2), 256>>>(s, Whhf, bhhf, Whhr, bhhr);
    attn_score_kernel<<<M_ / 128, 256>>>(0, Wword, bword, pword);
    word_vec_kernel<<<B_, 128>>>();
    attn_score_kernel<<<B_ / 128, 256>>>(1, Wsent, bsent, psent);
    sent_fc_scatter_kernel<<<NB_, 64>>>(pairs, fcW, fcb, out);
}

// round 10
// speedup vs baseline: 1.3572x; 1.3572x over previous
#include <cuda_runtime.h>
#include <math.h>

#define NB_ 512
#define MS_ 8
#define T_  64
#define IN_ 360
#define H_  230
#define H2_ 460
#define H3_ 690
#define OUT_ 53
#define ENT_ 8
#define B_  4096
#define M_  (B_ * T_)
#define KIP_ 368
#define KGR_ 240
#define KAT_ 464
#define WTC_ 768
#define WIC_ 704

typedef unsigned long long u64;

__device__ float g_xg[(size_t)2 * M_ * H3_];
__device__ float g_bagT[(size_t)KIP_ * M_];
__device__ float g_outT[(size_t)KAT_ * M_];
__device__ float g_hT[2 * 2 * KGR_ * B_];
__device__ float g_Wt[2 * KGR_ * WTC_];
__device__ float g_WihT[2 * KIP_ * WIC_];
__device__ float g_wvT[KAT_ * B_];
__device__ float g_score[M_];
__device__ float g_score2[B_];

__device__ __forceinline__ u64 pack_dup(float b) {
    u64 r; asm("mov.b64 %0, {%1, %2};" : "=l"(r) : "f"(b), "f"(b)); return r;
}
__device__ __forceinline__ void fma2(u64& acc, u64 a, u64 b) {
    asm("fma.rn.f32x2 %0, %1, %2, %0;" : "+l"(acc) : "l"(a), "l"(b));
}
__device__ __forceinline__ float2 unpk(u64 v) {
    float lo, hi; asm("mov.b64 {%0, %1}, %2;" : "=f"(lo), "=f"(hi) : "l"(v));
    return make_float2(lo, hi);
}
__device__ __forceinline__ float sigm(float x) { return 1.0f / (1.0f + __expf(-x)); }
__device__ __forceinline__ float tanh_f(float x) { return 1.0f - 2.0f / (1.0f + __expf(2.0f * x)); }
__device__ __forceinline__ void cp16(void* d, const void* s) {
    unsigned sa = (unsigned)__cvta_generic_to_shared(d);
    asm volatile("cp.async.cg.shared.global [%0], [%1], 16;" :: "r"(sa), "l"(s));
}
__device__ __forceinline__ void cp16z(void* d, const void* s, int bytes) {
    unsigned sa = (unsigned)__cvta_generic_to_shared(d);
    asm volatile("cp.async.cg.shared.global [%0], [%1], 16, %2;" :: "r"(sa), "l"(s), "r"(bytes));
}
#define CP_COMMIT() asm volatile("cp.async.commit_group;")
#define CP_WAIT1()  asm volatile("cp.async.wait_group 1;")

__global__ void zero_prep_kernel(float* out, int n_out) {
    size_t st = (size_t)gridDim.x * blockDim.x;
    size_t i0 = (size_t)blockIdx.x * blockDim.x + threadIdx.x;
    for (size_t i = i0; i < (size_t)n_out; i += st) out[i] = 0.f;
    for (size_t i = i0; i < (size_t)2 * 2 * KGR_ * B_; i += st) g_hT[i] = 0.f;
    for (size_t i = i0; i < (size_t)(KIP_ - IN_) * M_; i += st) g_bagT[(size_t)IN_ * M_ + i] = 0.f;
    for (size_t i = i0; i < (size_t)(KAT_ - H2_) * M_; i += st) g_outT[(size_t)H2_ * M_ + i] = 0.f;
    for (size_t i = i0; i < (size_t)(KAT_ - H2_) * B_; i += st) g_wvT[(size_t)H2_ * B_ + i] = 0.f;
}

__global__ void transpose_w_kernel(const float* __restrict__ Whhf, const float* __restrict__ Whhr,
                                   const float* __restrict__ Wihf, const float* __restrict__ Wihr) {
    size_t st = (size_t)gridDim.x * blockDim.x;
    size_t i0 = (size_t)blockIdx.x * blockDim.x + threadIdx.x;
    for (size_t i = i0; i < (size_t)2 * KGR_ * WTC_; i += st) {
        int dir = (int)(i / (KGR_ * WTC_)), rem = (int)(i % (KGR_ * WTC_));
        int k = rem / WTC_, j = rem % WTC_, g = j >> 8, c = j & 255;
        const float* Wh = dir ? Whhr : Whhf;
        g_Wt[i] = (k < H_ && c < H_) ? Wh[(size_t)(g * H_ + c) * H_ + k] : 0.f;
    }
    for (size_t i = i0; i < (size_t)2 * KIP_ * WIC_; i += st) {
        int dir = (int)(i / (KIP_ * WIC_)), rem = (int)(i % (KIP_ * WIC_));
        int k = rem / WIC_, n = rem % WIC_;
        const float* Wi = dir ? Wihr : Wihf;
        g_WihT[i] = (k < IN_ && n < H3_) ? Wi[(size_t)n * IN_ + k] : 0.f;
    }
}

__global__ __launch_bounds__(256) void transpose_bag_kernel(const float* __restrict__ bag) {
    __shared__ float tile[32][33];
    int m0 = blockIdx.x * 32, k0 = blockIdx.y * 32;
    int cIn = threadIdx.x & 31, rIn = threadIdx.x >> 5;
#pragma unroll
    for (int rr = 0; rr < 4; rr++) {
        int r = rIn + rr * 8, gk = k0 + cIn;
        tile[r][cIn] = (gk < IN_) ? bag[(size_t)(m0 + r) * IN_ + gk] : 0.f;
    }
    __syncthreads();
#pragma unroll
    for (int rr = 0; rr < 4; rr++) {
        int r = rIn + rr * 8, gk = k0 + r;
        if (gk < IN_) g_bagT[(size_t)gk * M_ + m0 + cIn] = tile[cIn][r];
    }
}

// ---- input projection: xg[t][b][3H] = x @ W_ih^T + b_ih (per dir) ----
__global__ __launch_bounds__(256, 3) void input_proj_kernel(
    const float* __restrict__ bf, const float* __restrict__ br)
{
    const int dir = blockIdx.z;
    const float* __restrict__ bias = dir ? br : bf;
    float* __restrict__ xg = g_xg + (size_t)dir * M_ * H3_;
    const int n0 = blockIdx.x * 64;
    const size_t m0 = (size_t)blockIdx.y * 128;

    __shared__ __align__(16) float smA[3 * 16 * 128];
    __shared__ __align__(16) float smB[3 * 16 * 64];
#define IPA(st,k,r) smA[((st)*16+(k))*128+(r)]
#define IPB(st,k,n) smB[((st)*16+(k))*64+(n)]
    const int tid = threadIdx.x, tx = tid & 15, ty = tid >> 4;
    const int aK0 = tid >> 5, aM = (tid & 31) * 4, aK1 = aK0 + 8;
    const int bK = tid >> 4, bN = (tid & 15) * 4;
    const float* aS0 = g_bagT + (size_t)aK0 * M_ + m0 + aM;
    const float* aS1 = g_bagT + (size_t)aK1 * M_ + m0 + aM;
    const float* bS  = g_WihT + (size_t)dir * KIP_ * WIC_ + (size_t)bK * WIC_ + n0 + bN;

    u64 acc[4][4];
#pragma unroll
    for (int i = 0; i < 4; i++)
#pragma unroll
        for (int j = 0; j < 4; j++) acc[i][j] = 0ull;

    const int NST = KIP_ / 16;  // 23
#pragma unroll
    for (int st = 0; st < 2; st++) {
        cp16(&IPA(st, aK0, aM), aS0); aS0 += (size_t)16 * M_;
        cp16(&IPA(st, aK1, aM), aS1); aS1 += (size_t)16 * M_;
        cp16(&IPB(st, bK, bN), bS);   bS  += (size_t)16 * WIC_;
        CP_COMMIT();
    }
    for (int it = 0; it < NST; it++) {
        CP_WAIT1();
        __syncthreads();
        if (it + 2 < NST) {
            const int st = (it + 2) % 3;
            cp16(&IPA(st, aK0, aM), aS0); aS0 += (size_t)16 * M_;
            cp16(&IPA(st, aK1, aM), aS1); aS1 += (size_t)16 * M_;
            cp16(&IPB(st, bK, bN), bS);   bS  += (size_t)16 * WIC_;
        }
        CP_COMMIT();
        const int cur = it % 3;
#pragma unroll
        for (int k = 0; k < 16; k++) {
            ulonglong2 A0 = *(const ulonglong2*)&IPA(cur, k, ty * 8);
            ulonglong2 A1 = *(const ulonglong2*)&IPA(cur, k, ty * 8 + 4);
            u64 a[4] = {A0.x, A0.y, A1.x, A1.y};
#pragma unroll
            for (int j = 0; j < 4; j++) {
                u64 bb = pack_dup(IPB(cur, k, j * 16 + tx));
#pragma unroll
                for (int i = 0; i < 4; i++) fma2(acc[i][j], a[i], bb);
            }
        }
    }
#pragma unroll
    for (int j = 0; j < 4; j++) {
        int n = n0 + j * 16 + tx;
        if (n >= H3_) continue;
        float bi = bias[n];
#pragma unroll
        for (int i = 0; i < 4; i++) {
            float2 v = unpk(acc[i][j]);
            int mm = (int)m0 + ty * 8 + i * 2;       // mm = b*T + t
            size_t r0 = ((size_t)(mm & 63) * B_ + (size_t)(mm >> 6)) * H3_;
            size_t r1 = ((size_t)((mm + 1) & 63) * B_ + (size_t)((mm + 1) >> 6)) * H3_;
            xg[r0 + n] = v.x + bi;
            xg[r1 + n] = v.y + bi;
        }
    }
#undef IPA
#undef IPB
}

// ---- GRU step: gates = hT^T @ WhhT, fused nonlinearity ----
__global__ __launch_bounds__(256, 3) void gru_step_kernel(int s,
    const float* __restrict__ bhf, const float* __restrict__ bhr)
{
    const int dir = blockIdx.z;
    const int tIdx = dir ? (T_ - 1 - s) : s;
    const float* __restrict__ bhh = dir ? bhr : bhf;
    const float* __restrict__ hTprev = g_hT + ((size_t)dir * 2 + (s & 1)) * KGR_ * B_;
    float*       __restrict__ hTnext = g_hT + ((size_t)dir * 2 + ((s + 1) & 1)) * KGR_ * B_;
    const float* __restrict__ xg = g_xg + (size_t)dir * M_ * H3_;
    const float* __restrict__ Wtd = g_Wt + (size_t)dir * KGR_ * WTC_;
    const int c0 = blockIdx.x * 32;
    const size_t m0 = (size_t)blockIdx.y * 128;

    __shared__ __align__(16) float smA[3 * 16 * 128];
    __shared__ __align__(16) float smB[3 * 16 * 96];
#define GRA(st,k,r)   smA[((st)*16+(k))*128+(r)]
#define GRB(st,k,g,c) smB[(((st)*16+(k))*3+(g))*32+(c)]
    const int tid = threadIdx.x, tx = tid & 15, ty = tid >> 4;
    const int aK0 = tid >> 5, aM = (tid & 31) * 4, aK1 = aK0 + 8;
    const float* aS0 = hTprev + (size_t)aK0 * B_ + m0 + aM;
    const float* aS1 = hTprev + (size_t)aK1 * B_ + m0 + aM;
    const int id1 = 256 + tid;
    const int bK0 = tid / 24, bJ0 = tid % 24, bK1 = id1 / 24, bJ1 = id1 % 24;
    const int bG0 = bJ0 >> 3, bC0 = (bJ0 & 7) * 4, bG1 = bJ1 >> 3, bC1 = (bJ1 & 7) * 4;
    const float* bS0 = Wtd + (size_t)bK0 * WTC_ + bG0 * 256 + c0 + bC0;
    const float* bS1 = Wtd + (size_t)bK1 * WTC_ + bG1 * 256 + c0 + bC1;
    const bool b1ok = tid < 128;

    u64 acc[4][6];
#pragma unroll
    for (int i = 0; i < 4; i++)
#pragma unroll
        for (int j = 0; j < 6; j++) acc[i][j] = 0ull;

    const int NST = KGR_ / 16;  // 15
#pragma unroll
    for (int st = 0; st < 2; st++) {
        cp16(&GRA(st, aK0, aM), aS0); aS0 += (size_t)16 * B_;
        cp16(&GRA(st, aK1, aM), aS1); aS1 += (size_t)16 * B_;
        cp16(&GRB(st, bK0, bG0, bC0), bS0); bS0 += (size_t)16 * WTC_;
        if (b1ok) { cp16(&GRB(st, bK1, bG1, bC1), bS1); bS1 += (size_t)16 * WTC_; }
        CP_COMMIT();
    }
    for (int it = 0; it < NST; it++) {
        CP_WAIT1();
        __syncthreads();
        if (it + 2 < NST) {
            const int st = (it + 2) % 3;
            cp16(&GRA(st, aK0, aM), aS0); aS0 += (size_t)16 * B_;
            cp16(&GRA(st, aK1, aM), aS1); aS1 += (size_t)16 * B_;
            cp16(&GRB(st, bK0, bG0, bC0), bS0); bS0 += (size_t)16 * WTC_;
            if (b1ok) { cp16(&GRB(st, bK1, bG1, bC1), bS1); bS1 += (size_t)16 * WTC_; }
        }
        CP_COMMIT();
        const int cur = it % 3;
#pragma unroll
        for (int k = 0; k < 16; k++) {
            ulonglong2 A0 = *(const ulonglong2*)&GRA(cur, k, ty * 8);
            ulonglong2 A1 = *(const ulonglong2*)&GRA(cur, k, ty * 8 + 4);
            u64 a[4] = {A0.x, A0.y, A1.x, A1.y};
#pragma unroll
            for (int g = 0; g < 3; g++) {
                float2 w2 = *(const float2*)&GRB(cur, k, g, tx * 2);
                u64 b0 = pack_dup(w2.x);
                u64 b1 = pack_dup(w2.y);
#pragma unroll
                for (int i = 0; i < 4; i++) fma2(acc[i][g * 2],     a[i], b0);
#pragma unroll
                for (int i = 0; i < 4; i++) fma2(acc[i][g * 2 + 1], a[i], b1);
            }
        }
    }

    const int c = c0 + tx * 2;
    if (c >= H_) return;
    const float br0 = bhh[c],          br1 = bhh[c + 1];
    const float bz0 = bhh[H_ + c],     bz1 = bhh[H_ + c + 1];
    const float bq0 = bhh[2 * H_ + c], bq1 = bhh[2 * H_ + c + 1];

    float hp0[8], hp1[8], hv0[8], hv1[8];
    {
        const float* h0p = hTprev + (size_t)c * B_ + m0 + ty * 8;
        const float* h1p = hTprev + (size_t)(c + 1) * B_ + m0 + ty * 8;
        *(float4*)&hp0[0] = *(const float4*)h0p;
        *(float4*)&hp0[4] = *(const float4*)(h0p + 4);
        *(float4*)&hp1[0] = *(const float4*)h1p;
        *(float4*)&hp1[4] = *(const float4*)(h1p + 4);
    }
#pragma unroll
    for (int i = 0; i < 4; i++) {
        float2 vr0 = unpk(acc[i][0]), vr1 = unpk(acc[i][1]);
        float2 vz0 = unpk(acc[i][2]), vz1 = unpk(acc[i][3]);
        float2 vq0 = unpk(acc[i][4]), vq1 = unpk(acc[i][5]);
#pragma unroll
        for (int half = 0; half < 2; half++) {
            int j = i * 2 + half;
            size_t b = m0 + ty * 8 + j;
            size_t xbase = ((size_t)tIdx * B_ + b) * H3_;
            float2 axr = *(const float2*)&xg[xbase + c];
            float2 axz = *(const float2*)&xg[xbase + H_ + c];
            float2 axn = *(const float2*)&xg[xbase + 2 * H_ + c];
            float ar0 = half ? vr0.y : vr0.x, ar1 = half ? vr1.y : vr1.x;
            float az0 = half ? vz0.y : vz0.x, az1 = half ? vz1.y : vz1.x;
            float aq0 = half ? vq0.y : vq0.x, aq1 = half ? vq1.y : vq1.x;
            float r0 = sigm(axr.x + ar0 + br0);
            float r1 = sigm(axr.y + ar1 + br1);
            float z0 = sigm(axz.x + az0 + bz0);
            float z1 = sigm(axz.y + az1 + bz1);
            float q0 = tanh_f(axn.x + r0 * (aq0 + bq0));
            float q1 = tanh_f(axn.y + r1 * (aq1 + bq1));
            hv0[j] = (1.f - z0) * q0 + z0 * hp0[j];
            hv1[j] = (1.f - z1) * q1 + z1 * hp1[j];
        }
    }
    float* hn0 = hTnext + (size_t)c * B_ + m0 + ty * 8;
    float* hn1 = hTnext + (size_t)(c + 1) * B_ + m0 + ty * 8;
    *(float4*)hn0       = make_float4(hv0[0], hv0[1], hv0[2], hv0[3]);
    *(float4*)(hn0 + 4) = make_float4(hv0[4], hv0[5], hv0[6], hv0[7]);
    *(float4*)hn1       = make_float4(hv1[0], hv1[1], hv1[2], hv1[3]);
    *(float4*)(hn1 + 4) = make_float4(hv1[4], hv1[5], hv1[6], hv1[7]);

    size_t ocol = (size_t)tIdx * B_ + m0 + ty * 8;
    float* ot0 = g_outT + (size_t)(dir * H_ + c) * M_ + ocol;
    float* ot1 = g_outT + (size_t)(dir * H_ + c + 1) * M_ + ocol;
    *(float4*)ot0       = make_float4(hv0[0], hv0[1], hv0[2], hv0[3]);
    *(float4*)(ot0 + 4) = make_float4(hv0[4], hv0[5], hv0[6], hv0[7]);
    *(float4*)ot1       = make_float4(hv1[0], hv1[1], hv1[2], hv1[3]);
    *(float4*)(ot1 + 4) = make_float4(hv1[4], hv1[5], hv1[6], hv1[7]);
#undef GRA
#undef GRB
}

// ---- fused attention score: score[m] = sum_n tanh((A@W)[m,n]+b[n])*p[n] ----
__global__ __launch_bounds__(256, 3) void attn_score_kernel(
    const float* __restrict__ A, size_t ldA,
    const float* __restrict__ W, const float* __restrict__ bias,
    const float* __restrict__ proj, float* __restrict__ score)
{
    const size_t m0 = (size_t)blockIdx.x * 128;
    __shared__ __align__(16) float smA[3 * 16 * 128];
    __shared__ __align__(16) float smB[3 * 16 * 64];
    __shared__ float red[128][16];
#define ATA(st,k,r) smA[((st)*16+(k))*128+(r)]
#define ATB(st,k,n) smB[((st)*16+(k))*64+(n)]
    const int tid = threadIdx.x, tx = tid & 15, ty = tid >> 4;
    const int aK0 = tid >> 5, aM = (tid & 31) * 4, aK1 = aK0 + 8;
    const int bK = tid >> 4, bN = (tid & 15) * 4;
    const float* aB0 = A + (size_t)aK0 * ldA + m0 + aM;
    const float* aB1 = A + (size_t)aK1 * ldA + m0 + aM;

    float sp[8];
#pragma unroll
    for (int i = 0; i < 8; i++) sp[i] = 0.0f;

    const int NST = KAT_ / 16;  // 29
    for (int n0 = 0; n0 < H2_; n0 += 64) {
        u64 acc[4][4];
#pragma unroll
        for (int i = 0; i < 4; i++)
#pragma unroll
            for (int j = 0; j < 4; j++) acc[i][j] = 0ull;

        int rem = H2_ - (n0 + bN);
        int nbytes = rem >= 4 ? 16 : (rem > 0 ? rem * 4 : 0);
        const float* aS0 = aB0;
        const float* aS1 = aB1;

        __syncthreads();
#pragma unroll
        for (int st = 0; st < 2; st++) {
            cp16(&ATA(st, aK0, aM), aS0); aS0 += (size_t)16 * ldA;
            cp16(&ATA(st, aK1, aM), aS1); aS1 += (size_t)16 * ldA;
            int kk = st * 16 + bK;
            int bytes = (kk < H2_) ? nbytes : 0;
            const float* src = bytes ? (W + (size_t)kk * H2_ + n0 + bN) : W;
            cp16z(&ATB(st, bK, bN), src, bytes);
            CP_COMMIT();
        }
        for (int it = 0; it < NST; it++) {
            CP_WAIT1();
            __syncthreads();
            if (it + 2 < NST) {
                const int st = (it + 2) % 3;
                cp16(&ATA(st, aK0, aM), aS0); aS0 += (size_t)16 * ldA;
                cp16(&ATA(st, aK1, aM), aS1); aS1 += (size_t)16 * ldA;
                int kk = (it + 2) * 16 + bK;
                int bytes = (kk < H2_) ? nbytes : 0;
                const float* src = bytes ? (W + (size_t)kk * H2_ + n0 + bN) : W;
                cp16z(&ATB(st, bK, bN), src, bytes);
            }
            CP_COMMIT();
            const int cur = it % 3;
#pragma unroll
            for (int k = 0; k < 16; k++) {
                ulonglong2 A0 = *(const ulonglong2*)&ATA(cur, k, ty * 8);
                ulonglong2 A1 = *(const ulonglong2*)&ATA(cur, k, ty * 8 + 4);
                u64 a[4] = {A0.x, A0.y, A1.x, A1.y};
#pragma unroll
                for (int j = 0; j < 4; j++) {
                    u64 bb = pack_dup(ATB(cur, k, j * 16 + tx));
#pragma unroll
                    for (int i = 0; i < 4; i++) fma2(acc[i][j], a[i], bb);
                }
            }
        }
#pragma unroll
        for (int j = 0; j < 4; j++) {
            int n = n0 + j * 16 + tx;
            if (n >= H2_) continue;
            float bi = bias[n], pj = proj[n];
#pragma unroll
            for (int i = 0; i < 4; i++) {
                float2 v = unpk(acc[i][j]);
                sp[i * 2]     += tanh_f(v.x + bi) * pj;
                sp[i * 2 + 1] += tanh_f(v.y + bi) * pj;
            }
        }
    }
    __syncthreads();
#pragma unroll
    for (int i = 0; i < 8; i++) red[ty * 8 + i][tx] = sp[i];
    __syncthreads();
    if (tid < 128) {
        float s = 0.f;
#pragma unroll
        for (int j = 0; j < 16; j++) s += red[tid][j];
        score[m0 + tid] = s;
    }
#undef ATA
#undef ATB
}

// ---- word softmax over t + weighted sum -> g_wvT[h][b] ----
__global__ __launch_bounds__(128) void word_vec_kernel() {
    const int tid = threadIdx.x;
    const int b = blockIdx.x * 128 + tid;
    const int h0 = blockIdx.y * 58;
    const int hend = min(h0 + 58, H2_);
    __shared__ float al[T_][128];

    float mx = -1e30f;
#pragma unroll 8
    for (int t = 0; t < T_; t++) {
        float s = g_score[(size_t)t * B_ + b];
        al[t][tid] = s;
        mx = fmaxf(mx, s);
    }
    float sm = 0.f;
#pragma unroll 8
    for (int t = 0; t < T_; t++) sm += __expf(al[t][tid] - mx);
    float inv = 1.0f / sm;
#pragma unroll 8
    for (int t = 0; t < T_; t++) al[t][tid] = __expf(al[t][tid] - mx) * inv;

    for (int h = h0; h < hend; h++) {
        const float* row = g_outT + (size_t)h * M_ + b;
        float acc = 0.f;
#pragma unroll 8
        for (int t = 0; t < T_; t++) acc += al[t][tid] * row[(size_t)t * B_];
        g_wvT[(size_t)h * B_ + b] = acc;
    }
}

// ---- sentence softmax + sent_vec + FC + scatter ----
__global__ __launch_bounds__(128) void sent_fc_scatter_kernel(
    const int* __restrict__ pairs, const float* __restrict__ fcW,
    const float* __restrict__ fcb, float* __restrict__ out)
{
    int nb = blockIdx.x;
    int tid = threadIdx.x;
    __shared__ float sv[H2_];

    float sc[MS_], mx = -1e30f;
#pragma unroll
    for (int s = 0; s < MS_; s++) { sc[s] = g_score2[nb * MS_ + s]; mx = fmaxf(mx, sc[s]); }
    float sm = 0.f;
#pragma unroll
    for (int s = 0; s < MS_; s++) sm += __expf(sc[s] - mx);
    float be[MS_];
#pragma unroll
    for (int s = 0; s < MS_; s++) be[s] = __expf(sc[s] - mx) / sm;

    for (int h = tid; h < H2_; h += blockDim.x) {
        const float* wp = g_wvT + (size_t)h * B_ + nb * MS_;
        float4 wa = *(const float4*)wp;
        float4 wb = *(const float4*)(wp + 4);
        sv[h] = be[0] * wa.x + be[1] * wa.y + be[2] * wa.z + be[3] * wa.w
              + be[4] * wb.x + be[5] * wb.y + be[6] * wb.z + be[7] * wb.w;
    }
    __syncthreads();

    int d = pairs[nb * 3], e1 = pairs[nb * 3 + 1], e2 = pairs[nb * 3 + 2];
    size_t base = (((size_t)d * ENT_ + e1) * ENT_ + e2) * OUT_;
    for (int o = tid; o < OUT_; o += blockDim.x) {
        float acc = fcb[o];
        for (int k = 0; k < H2_; k++) acc += sv[k] * fcW[(size_t)o * H2_ + k];
        out[base + o] = acc;
    }
}

extern "C" void kernel_launch(void* const* d_in, const int* in_sizes, int n_in,
                              void* d_out, int out_size) {
    const float* bag   = (const float*)d_in[0];
    const float* Wihf  = (const float*)d_in[1];
    const float* Whhf  = (const float*)d_in[2];
    const float* bihf  = (const float*)d_in[3];
    const float* bhhf  = (const float*)d_in[4];
    const float* Wihr  = (const float*)d_in[5];
    const float* Whhr  = (const float*)d_in[6];
    const float* bihr  = (const float*)d_in[7];
    const float* bhhr  = (const float*)d_in[8];
    const float* Wword = (const float*)d_in[9];
    const float* bword = (const float*)d_in[10];
    const float* pword = (const float*)d_in[11];
    const float* Wsent = (const float*)d_in[12];
    const float* bsent = (const float*)d_in[13];
    const float* psent = (const float*)d_in[14];
    const float* fcW   = (const float*)d_in[15];
    const float* fcb   = (const float*)d_in[16];
    const int*   pairs = (const int*)d_in[17];
    float* out = (float*)d_out;

    float *d_outT, *d_wvT, *d_sc, *d_sc2;
    cudaGetSymbolAddress((void**)&d_outT, g_outT);
    cudaGetSymbolAddress((void**)&d_wvT,  g_wvT);
    cudaGetSymbolAddress((void**)&d_sc,   g_score);
    cudaGetSymbolAddress((void**)&d_sc2,  g_score2);

    zero_prep_kernel<<<2048, 256>>>(out, out_size);
    transpose_w_kernel<<<512, 256>>>(Whhf, Whhr, Wihf, Wihr);
    transpose_bag_kernel<<<dim3(M_ / 32, 12), 256>>>(bag);
    input_proj_kernel<<<dim3(11, 2048, 2), 256>>>(bihf, bihr);
    for (int s = 0; s < T_; s++)
        gru_step_kernel<<<dim3(8, 32, 2), 256>>>(s, bhhf, bhhr);
    attn_score_kernel<<<M_ / 128, 256>>>(d_outT, (size_t)M_, Wword, bword, pword, d_sc);
    word_vec_kernel<<<dim3(B_ / 128, 8), 128>>>();
    attn_score_kernel<<<B_ / 128, 256>>>(d_wvT, (size_t)B_, Wsent, bsent, psent, d_sc2);
    sent_fc_scatter_kernel<<<NB_, 128>>>(pairs, fcW, fcb, out);
}

// round 12
// speedup vs baseline: 1.7641x; 1.2998x over previous
#include <cuda_runtime.h>
#include <math.h>

#define NB_ 512
#define MS_ 8
#define T_  64
#define IN_ 360
#define H_  230
#define H2_ 460
#define H3_ 690
#define OUT_ 53
#define ENT_ 8
#define B_  4096
#define M_  (B_ * T_)
#define KIP_ 368
#define KGR_ 240
#define KAT_ 464
#define WTC_ 768
#define WIC_ 704

typedef unsigned long long u64;

__device__ float g_xg[(size_t)2 * M_ * H3_];
__device__ float g_bagT[(size_t)KIP_ * M_];
__device__ float g_outT[(size_t)KAT_ * M_];
__device__ float g_hT[2 * 2 * KGR_ * B_];
__device__ float g_Wt[2 * KGR_ * WTC_];
__device__ float g_WihT[2 * KIP_ * WIC_];
__device__ float g_wvT[KAT_ * B_];
__device__ float g_score[M_];
__device__ float g_score2[B_];

__device__ __forceinline__ u64 pack_dup(float b) {
    u64 r; asm("mov.b64 %0, {%1, %2};" : "=l"(r) : "f"(b), "f"(b)); return r;
}
__device__ __forceinline__ void fma2(u64& acc, u64 a, u64 b) {
    asm("fma.rn.f32x2 %0, %1, %2, %0;" : "+l"(acc) : "l"(a), "l"(b));
}
__device__ __forceinline__ float2 unpk(u64 v) {
    float lo, hi; asm("mov.b64 {%0, %1}, %2;" : "=f"(lo), "=f"(hi) : "l"(v));
    return make_float2(lo, hi);
}
__device__ __forceinline__ float sigm(float x) { return 1.0f / (1.0f + __expf(-x)); }
__device__ __forceinline__ float tanh_f(float x) { return 1.0f - 2.0f / (1.0f + __expf(2.0f * x)); }
__device__ __forceinline__ float tf32r(float x) {
    unsigned u;
    asm("cvt.rna.tf32.f32 %0, %1;" : "=r"(u) : "f"(x));
    return __uint_as_float(u);
}
__device__ __forceinline__ void cp16(void* d, const void* s) {
    unsigned sa = (unsigned)__cvta_generic_to_shared(d);
    asm volatile("cp.async.cg.shared.global [%0], [%1], 16;" :: "r"(sa), "l"(s));
}
__device__ __forceinline__ void cp16z(void* d, const void* s, int bytes) {
    unsigned sa = (unsigned)__cvta_generic_to_shared(d);
    asm volatile("cp.async.cg.shared.global [%0], [%1], 16, %2;" :: "r"(sa), "l"(s), "r"(bytes));
}
#define CP_COMMIT() asm volatile("cp.async.commit_group;")
#define CP_WAIT1()  asm volatile("cp.async.wait_group 1;")

__global__ void zero_prep_kernel(float* out, int n_out) {
    size_t st = (size_t)gridDim.x * blockDim.x;
    size_t i0 = (size_t)blockIdx.x * blockDim.x + threadIdx.x;
    for (size_t i = i0; i < (size_t)n_out; i += st) out[i] = 0.f;
    for (size_t i = i0; i < (size_t)2 * 2 * KGR_ * B_; i += st) g_hT[i] = 0.f;
    for (size_t i = i0; i < (size_t)(KIP_ - IN_) * M_; i += st) g_bagT[(size_t)IN_ * M_ + i] = 0.f;
    for (size_t i = i0; i < (size_t)(KAT_ - H2_) * M_; i += st) g_outT[(size_t)H2_ * M_ + i] = 0.f;
    for (size_t i = i0; i < (size_t)(KAT_ - H2_) * B_; i += st) g_wvT[(size_t)H2_ * B_ + i] = 0.f;
}

__global__ void transpose_w_kernel(const float* __restrict__ Whhf, const float* __restrict__ Whhr,
                                   const float* __restrict__ Wihf, const float* __restrict__ Wihr) {
    size_t st = (size_t)gridDim.x * blockDim.x;
    size_t i0 = (size_t)blockIdx.x * blockDim.x + threadIdx.x;
    for (size_t i = i0; i < (size_t)2 * KGR_ * WTC_; i += st) {
        int dir = (int)(i / (KGR_ * WTC_)), rem = (int)(i % (KGR_ * WTC_));
        int k = rem / WTC_, j = rem % WTC_, g = j >> 8, c = j & 255;
        const float* Wh = dir ? Whhr : Whhf;
        g_Wt[i] = (k < H_ && c < H_) ? Wh[(size_t)(g * H_ + c) * H_ + k] : 0.f;
    }
    for (size_t i = i0; i < (size_t)2 * KIP_ * WIC_; i += st) {
        int dir = (int)(i / (KIP_ * WIC_)), rem = (int)(i % (KIP_ * WIC_));
        int k = rem / WIC_, n = rem % WIC_;
        const float* Wi = dir ? Wihr : Wihf;
        g_WihT[i] = (k < IN_ && n < H3_) ? tf32r(Wi[(size_t)n * IN_ + k]) : 0.f;
    }
}

__global__ __launch_bounds__(256) void transpose_bag_kernel(const float* __restrict__ bag) {
    __shared__ float tile[32][33];
    int m0 = blockIdx.x * 32, k0 = blockIdx.y * 32;
    int cIn = threadIdx.x & 31, rIn = threadIdx.x >> 5;
#pragma unroll
    for (int rr = 0; rr < 4; rr++) {
        int r = rIn + rr * 8, gk = k0 + cIn;
        tile[r][cIn] = (gk < IN_) ? bag[(size_t)(m0 + r) * IN_ + gk] : 0.f;
    }
    __syncthreads();
#pragma unroll
    for (int rr = 0; rr < 4; rr++) {
        int r = rIn + rr * 8, gk = k0 + r;
        if (gk < IN_) g_bagT[(size_t)gk * M_ + m0 + cIn] = tf32r(tile[cIn][r]);
    }
}

// ---- input projection via TF32 mma.sync: xg[t][b][3H] = x @ W_ih^T + b_ih ----
// Block 128m x 64n, K staged 16, 3-stage cp.async. 8 warps = 4m x 2n, warp 32x32.
__global__ __launch_bounds__(256, 3) void input_proj_kernel(
    const float* __restrict__ bf, const float* __restrict__ br)
{
    const int dir = blockIdx.z;
    const float* __restrict__ bias = dir ? br : bf;
    float* __restrict__ xg = g_xg + (size_t)dir * M_ * H3_;
    const int n0 = blockIdx.x * 64;
    const size_t m0 = (size_t)blockIdx.y * 128;

    __shared__ __align__(16) float smA[3][16][136];   // stride 136 -> banks (8k+m)%32
    __shared__ __align__(16) float smB[3][16][72];    // stride 72  -> banks (8k+n)%32

    const int tid = threadIdx.x;
    const int lane = tid & 31, warp = tid >> 5;
    const int wm = (warp & 3) * 32, wn = (warp >> 2) * 32;
    const int lq = lane & 3, rq = lane >> 2;

    const int aK0 = tid >> 5, aM4 = (tid & 31) * 4, aK1 = aK0 + 8;
    const int bK = tid >> 4, bN4 = (tid & 15) * 4;
    const float* aS0 = g_bagT + (size_t)aK0 * M_ + m0 + aM4;
    const float* aS1 = g_bagT + (size_t)aK1 * M_ + m0 + aM4;
    const float* bS  = g_WihT + (size_t)dir * KIP_ * WIC_ + (size_t)bK * WIC_ + n0 + bN4;

    float acc[2][4][4];
#pragma unroll
    for (int i = 0; i < 2; i++)
#pragma unroll
        for (int j = 0; j < 4; j++)
#pragma unroll
            for (int q = 0; q < 4; q++) acc[i][j][q] = 0.f;

    const int NST = KIP_ / 16;  // 23
#pragma unroll
    for (int st = 0; st < 2; st++) {
        cp16(&smA[st][aK0][aM4], aS0); aS0 += (size_t)16 * M_;
        cp16(&smA[st][aK1][aM4], aS1); aS1 += (size_t)16 * M_;
        cp16(&smB[st][bK][bN4], bS);   bS  += (size_t)16 * WIC_;
        CP_COMMIT();
    }
    for (int it = 0; it < NST; it++) {
        CP_WAIT1();
        __syncthreads();
        if (it + 2 < NST) {
            const int st = (it + 2) % 3;
            cp16(&smA[st][aK0][aM4], aS0); aS0 += (size_t)16 * M_;
            cp16(&smA[st][aK1][aM4], aS1); aS1 += (size_t)16 * M_;
            cp16(&smB[st][bK][bN4], bS);   bS  += (size_t)16 * WIC_;
        }
        CP_COMMIT();
        const int cur = it % 3;
#pragma unroll
        for (int k8 = 0; k8 < 16; k8 += 8) {
            const int kr = k8 + lq;
            unsigned af[2][4], bfr[4][2];
#pragma unroll
            for (int i = 0; i < 2; i++) {
                int rm = wm + i * 16 + rq;
                af[i][0] = __float_as_uint(smA[cur][kr][rm]);
                af[i][1] = __float_as_uint(smA[cur][kr][rm + 8]);
                af[i][2] = __float_as_uint(smA[cur][kr + 4][rm]);
                af[i][3] = __float_as_uint(smA[cur][kr + 4][rm + 8]);
            }
#pragma unroll
            for (int j = 0; j < 4; j++) {
                int nb = wn + j * 8 + rq;
                bfr[j][0] = __float_as_uint(smB[cur][kr][nb]);
                bfr[j][1] = __float_as_uint(smB[cur][kr + 4][nb]);
            }
#pragma unroll
            for (int i = 0; i < 2; i++)
#pragma unroll
                for (int j = 0; j < 4; j++)
                    asm("mma.sync.aligned.m16n8k8.row.col.f32.tf32.tf32.f32 "
                        "{%0,%1,%2,%3}, {%4,%5,%6,%7}, {%8,%9}, {%0,%1,%2,%3};"
                        : "+f"(acc[i][j][0]), "+f"(acc[i][j][1]),
                          "+f"(acc[i][j][2]), "+f"(acc[i][j][3])
                        : "r"(af[i][0]), "r"(af[i][1]), "r"(af[i][2]), "r"(af[i][3]),
                          "r"(bfr[j][0]), "r"(bfr[j][1]));
        }
    }

#pragma unroll
    for (int j = 0; j < 4; j++) {
        int n = n0 + wn + j * 8 + lq * 2;
        if (n >= H3_) continue;
        float b0v = bias[n], b1v = bias[n + 1];
#pragma unroll
        for (int i = 0; i < 2; i++) {
            int mmb = (int)m0 + wm + i * 16 + rq;
#pragma unroll
            for (int rr = 0; rr < 2; rr++) {
                int mm = mmb + rr * 8;               // mm = b*T + t
                size_t row = ((size_t)(mm & 63) * B_ + (size_t)(mm >> 6)) * H3_;
                *(float2*)&xg[row + n] =
                    make_float2(acc[i][j][rr * 2] + b0v, acc[i][j][rr * 2 + 1] + b1v);
            }
        }
    }
}

// ---- GRU step: gates = hT^T @ WhhT, fused nonlinearity ----
__global__ __launch_bounds__(256, 3) void gru_step_kernel(int s,
    const float* __restrict__ bhf, const float* __restrict__ bhr)
{
    const int dir = blockIdx.z;
    const int tIdx = dir ? (T_ - 1 - s) : s;
    const float* __restrict__ bhh = dir ? bhr : bhf;
    const float* __restrict__ hTprev = g_hT + ((size_t)dir * 2 + (s & 1)) * KGR_ * B_;
    float*       __restrict__ hTnext = g_hT + ((size_t)dir * 2 + ((s + 1) & 1)) * KGR_ * B_;
    const float* __restrict__ xg = g_xg + (size_t)dir * M_ * H3_;
    const float* __restrict__ Wtd = g_Wt + (size_t)dir * KGR_ * WTC_;
    const int c0 = blockIdx.x * 32;
    const size_t m0 = (size_t)blockIdx.y * 128;

    __shared__ __align__(16) float smA[3 * 16 * 128];
    __shared__ __align__(16) float smB[3 * 16 * 96];
#define GRA(st,k,r)   smA[((st)*16+(k))*128+(r)]
#define GRB(st,k,g,c) smB[(((st)*16+(k))*3+(g))*32+(c)]
    const int tid = threadIdx.x, tx = tid & 15, ty = tid >> 4;
    const int aK0 = tid >> 5, aM = (tid & 31) * 4, aK1 = aK0 + 8;
    const float* aS0 = hTprev + (size_t)aK0 * B_ + m0 + aM;
    const float* aS1 = hTprev + (size_t)aK1 * B_ + m0 + aM;
    const int id1 = 256 + tid;
    const int bK0 = tid / 24, bJ0 = tid % 24, bK1 = id1 / 24, bJ1 = id1 % 24;
    const int bG0 = bJ0 >> 3, bC0 = (bJ0 & 7) * 4, bG1 = bJ1 >> 3, bC1 = (bJ1 & 7) * 4;
    const float* bS0 = Wtd + (size_t)bK0 * WTC_ + bG0 * 256 + c0 + bC0;
    const float* bS1 = Wtd + (size_t)bK1 * WTC_ + bG1 * 256 + c0 + bC1;
    const bool b1ok = tid < 128;

    u64 acc[4][6];
#pragma unroll
    for (int i = 0; i < 4; i++)
#pragma unroll
        for (int j = 0; j < 6; j++) acc[i][j] = 0ull;

    const int NST = KGR_ / 16;  // 15
#pragma unroll
    for (int st = 0; st < 2; st++) {
        cp16(&GRA(st, aK0, aM), aS0); aS0 += (size_t)16 * B_;
        cp16(&GRA(st, aK1, aM), aS1); aS1 += (size_t)16 * B_;
        cp16(&GRB(st, bK0, bG0, bC0), bS0); bS0 += (size_t)16 * WTC_;
        if (b1ok) { cp16(&GRB(st, bK1, bG1, bC1), bS1); bS1 += (size_t)16 * WTC_; }
        CP_COMMIT();
    }
    for (int it = 0; it < NST; it++) {
        CP_WAIT1();
        __syncthreads();
        if (it + 2 < NST) {
            const int st = (it + 2) % 3;
            cp16(&GRA(st, aK0, aM), aS0); aS0 += (size_t)16 * B_;
            cp16(&GRA(st, aK1, aM), aS1); aS1 += (size_t)16 * B_;
            cp16(&GRB(st, bK0, bG0, bC0), bS0); bS0 += (size_t)16 * WTC_;
            if (b1ok) { cp16(&GRB(st, bK1, bG1, bC1), bS1); bS1 += (size_t)16 * WTC_; }
        }
        CP_COMMIT();
        const int cur = it % 3;
#pragma unroll
        for (int k = 0; k < 16; k++) {
            ulonglong2 A0 = *(const ulonglong2*)&GRA(cur, k, ty * 8);
            ulonglong2 A1 = *(const ulonglong2*)&GRA(cur, k, ty * 8 + 4);
            u64 a[4] = {A0.x, A0.y, A1.x, A1.y};
#pragma unroll
            for (int g = 0; g < 3; g++) {
                float2 w2 = *(const float2*)&GRB(cur, k, g, tx * 2);
                u64 b0 = pack_dup(w2.x);
                u64 b1 = pack_dup(w2.y);
#pragma unroll
                for (int i = 0; i < 4; i++) fma2(acc[i][g * 2],     a[i], b0);
#pragma unroll
                for (int i = 0; i < 4; i++) fma2(acc[i][g * 2 + 1], a[i], b1);
            }
        }
    }

    const int c = c0 + tx * 2;
    if (c >= H_) return;
    const float br0 = bhh[c],          br1 = bhh[c + 1];
    const float bz0 = bhh[H_ + c],     bz1 = bhh[H_ + c + 1];
    const float bq0 = bhh[2 * H_ + c], bq1 = bhh[2 * H_ + c + 1];

    float hp0[8], hp1[8], hv0[8], hv1[8];
    {
        const float* h0p = hTprev + (size_t)c * B_ + m0 + ty * 8;
        const float* h1p = hTprev + (size_t)(c + 1) * B_ + m0 + ty * 8;
        *(float4*)&hp0[0] = *(const float4*)h0p;
        *(float4*)&hp0[4] = *(const float4*)(h0p + 4);
        *(float4*)&hp1[0] = *(const float4*)h1p;
        *(float4*)&hp1[4] = *(const float4*)(h1p + 4);
    }
#pragma unroll
    for (int i = 0; i < 4; i++) {
        float2 vr0 = unpk(acc[i][0]), vr1 = unpk(acc[i][1]);
        float2 vz0 = unpk(acc[i][2]), vz1 = unpk(acc[i][3]);
        float2 vq0 = unpk(acc[i][4]), vq1 = unpk(acc[i][5]);
#pragma unroll
        for (int half = 0; half < 2; half++) {
            int j = i * 2 + half;
            size_t b = m0 + ty * 8 + j;
            size_t xbase = ((size_t)tIdx * B_ + b) * H3_;
            float2 axr = *(const float2*)&xg[xbase + c];
            float2 axz = *(const float2*)&xg[xbase + H_ + c];
            float2 axn = *(const float2*)&xg[xbase + 2 * H_ + c];
            float ar0 = half ? vr0.y : vr0.x, ar1 = half ? vr1.y : vr1.x;
            float az0 = half ? vz0.y : vz0.x, az1 = half ? vz1.y : vz1.x;
            float aq0 = half ? vq0.y : vq0.x, aq1 = half ? vq1.y : vq1.x;
            float r0 = sigm(axr.x + ar0 + br0);
            float r1 = sigm(axr.y + ar1 + br1);
            float z0 = sigm(axz.x + az0 + bz0);
            float z1 = sigm(axz.y + az1 + bz1);
            float q0 = tanh_f(axn.x + r0 * (aq0 + bq0));
            float q1 = tanh_f(axn.y + r1 * (aq1 + bq1));
            hv0[j] = (1.f - z0) * q0 + z0 * hp0[j];
            hv1[j] = (1.f - z1) * q1 + z1 * hp1[j];
        }
    }
    float* hn0 = hTnext + (size_t)c * B_ + m0 + ty * 8;
    float* hn1 = hTnext + (size_t)(c + 1) * B_ + m0 + ty * 8;
    *(float4*)hn0       = make_float4(hv0[0], hv0[1], hv0[2], hv0[3]);
    *(float4*)(hn0 + 4) = make_float4(hv0[4], hv0[5], hv0[6], hv0[7]);
    *(float4*)hn1       = make_float4(hv1[0], hv1[1], hv1[2], hv1[3]);
    *(float4*)(hn1 + 4) = make_float4(hv1[4], hv1[5], hv1[6], hv1[7]);

    size_t ocol = (size_t)tIdx * B_ + m0 + ty * 8;
    float* ot0 = g_outT + (size_t)(dir * H_ + c) * M_ + ocol;
    float* ot1 = g_outT + (size_t)(dir * H_ + c + 1) * M_ + ocol;
    *(float4*)ot0       = make_float4(hv0[0], hv0[1], hv0[2], hv0[3]);
    *(float4*)(ot0 + 4) = make_float4(hv0[4], hv0[5], hv0[6], hv0[7]);
    *(float4*)ot1       = make_float4(hv1[0], hv1[1], hv1[2], hv1[3]);
    *(float4*)(ot1 + 4) = make_float4(hv1[4], hv1[5], hv1[6], hv1[7]);
#undef GRA
#undef GRB
}

// ---- fused attention score: score[m] = sum_n tanh((A@W)[m,n]+b[n])*p[n] ----
__global__ __launch_bounds__(256, 3) void attn_score_kernel(
    const float* __restrict__ A, size_t ldA,
    const float* __restrict__ W, const float* __restrict__ bias,
    const float* __restrict__ proj, float* __restrict__ score)
{
    const size_t m0 = (size_t)blockIdx.x * 128;
    __shared__ __align__(16) float smA[3 * 16 * 128];
    __shared__ __align__(16) float smB[3 * 16 * 64];
    __shared__ float red[128][16];
#define ATA(st,k,r) smA[((st)*16+(k))*128+(r)]
#define ATB(st,k,n) smB[((st)*16+(k))*64+(n)]
    const int tid = threadIdx.x, tx = tid & 15, ty = tid >> 4;
    const int aK0 = tid >> 5, aM = (tid & 31) * 4, aK1 = aK0 + 8;
    const int bK = tid >> 4, bN = (tid & 15) * 4;
    const float* aB0 = A + (size_t)aK0 * ldA + m0 + aM;
    const float* aB1 = A + (size_t)aK1 * ldA + m0 + aM;

    float sp[8];
#pragma unroll
    for (int i = 0; i < 8; i++) sp[i] = 0.0f;

    const int NST = KAT_ / 16;  // 29
    for (int n0 = 0; n0 < H2_; n0 += 64) {
        u64 acc[4][4];
#pragma unroll
        for (int i = 0; i < 4; i++)
#pragma unroll
            for (int j = 0; j < 4; j++) acc[i][j] = 0ull;

        int rem = H2_ - (n0 + bN);
        int nbytes = rem >= 4 ? 16 : (rem > 0 ? rem * 4 : 0);
        const float* aS0 = aB0;
        const float* aS1 = aB1;

        __syncthreads();
#pragma unroll
        for (int st = 0; st < 2; st++) {
            cp16(&ATA(st, aK0, aM), aS0); aS0 += (size_t)16 * ldA;
            cp16(&ATA(st, aK1, aM), aS1); aS1 += (size_t)16 * ldA;
            int kk = st * 16 + bK;
            int bytes = (kk < H2_) ? nbytes : 0;
            const float* src = bytes ? (W + (size_t)kk * H2_ + n0 + bN) : W;
            cp16z(&ATB(st, bK, bN), src, bytes);
            CP_COMMIT();
        }
        for (int it = 0; it < NST; it++) {
            CP_WAIT1();
            __syncthreads();
            if (it + 2 < NST) {
                const int st = (it + 2) % 3;
                cp16(&ATA(st, aK0, aM), aS0); aS0 += (size_t)16 * ldA;
                cp16(&ATA(st, aK1, aM), aS1); aS1 += (size_t)16 * ldA;
                int kk = (it + 2) * 16 + bK;
                int bytes = (kk < H2_) ? nbytes : 0;
                const float* src = bytes ? (W + (size_t)kk * H2_ + n0 + bN) : W;
                cp16z(&ATB(st, bK, bN), src, bytes);
            }
            CP_COMMIT();
            const int cur = it % 3;
#pragma unroll
            for (int k = 0; k < 16; k++) {
                ulonglong2 A0 = *(const ulonglong2*)&ATA(cur, k, ty * 8);
                ulonglong2 A1 = *(const ulonglong2*)&ATA(cur, k, ty * 8 + 4);
                u64 a[4] = {A0.x, A0.y, A1.x, A1.y};
#pragma unroll
                for (int j = 0; j < 4; j++) {
                    u64 bb = pack_dup(ATB(cur, k, j * 16 + tx));
#pragma unroll
                    for (int i = 0; i < 4; i++) fma2(acc[i][j], a[i], bb);
                }
            }
        }
#pragma unroll
        for (int j = 0; j < 4; j++) {
            int n = n0 + j * 16 + tx;
            if (n >= H2_) continue;
            float bi = bias[n], pj = proj[n];
#pragma unroll
            for (int i = 0; i < 4; i++) {
                float2 v = unpk(acc[i][j]);
                sp[i * 2]     += tanh_f(v.x + bi) * pj;
                sp[i * 2 + 1] += tanh_f(v.y + bi) * pj;
            }
        }
    }
    __syncthreads();
#pragma unroll
    for (int i = 0; i < 8; i++) red[ty * 8 + i][tx] = sp[i];
    __syncthreads();
    if (tid < 128) {
        float s = 0.f;
#pragma unroll
        for (int j = 0; j < 16; j++) s += red[tid][j];
        score[m0 + tid] = s;
    }
#undef ATA
#undef ATB
}

// ---- word softmax over t + weighted sum -> g_wvT[h][b] ----
__global__ __launch_bounds__(128) void word_vec_kernel() {
    const int tid = threadIdx.x;
    const int b = blockIdx.x * 128 + tid;
    const int h0 = blockIdx.y * 58;
    const int hend = min(h0 + 58, H2_);
    __shared__ float al[T_][128];

    float mx = -1e30f;
#pragma unroll 8
    for (int t = 0; t < T_; t++) {
        float s = g_score[(size_t)t * B_ + b];
        al[t][tid] = s;
        mx = fmaxf(mx, s);
    }
    float sm = 0.f;
#pragma unroll 8
    for (int t = 0; t < T_; t++) sm += __expf(al[t][tid] - mx);
    float inv = 1.0f / sm;
#pragma unroll 8
    for (int t = 0; t < T_; t++) al[t][tid] = __expf(al[t][tid] - mx) * inv;

    for (int h = h0; h < hend; h++) {
        const float* row = g_outT + (size_t)h * M_ + b;
        float acc = 0.f;
#pragma unroll 8
        for (int t = 0; t < T_; t++) acc += al[t][tid] * row[(size_t)t * B_];
        g_wvT[(size_t)h * B_ + b] = acc;
    }
}

// ---- sentence softmax + sent_vec + FC + scatter ----
__global__ __launch_bounds__(128) void sent_fc_scatter_kernel(
    const int* __restrict__ pairs, const float* __restrict__ fcW,
    const float* __restrict__ fcb, float* __restrict__ out)
{
    int nb = blockIdx.x;
    int tid = threadIdx.x;
    __shared__ float sv[H2_];

    float sc[MS_], mx = -1e30f;
#pragma unroll
    for (int s = 0; s < MS_; s++) { sc[s] = g_score2[nb * MS_ + s]; mx = fmaxf(mx, sc[s]); }
    float sm = 0.f;
#pragma unroll
    for (int s = 0; s < MS_; s++) sm += __expf(sc[s] - mx);
    float be[MS_];
#pragma unroll
    for (int s = 0; s < MS_; s++) be[s] = __expf(sc[s] - mx) / sm;

    for (int h = tid; h < H2_; h += blockDim.x) {
        const float* wp = g_wvT + (size_t)h * B_ + nb * MS_;
        float4 wa = *(const float4*)wp;
        float4 wb = *(const float4*)(wp + 4);
        sv[h] = be[0] * wa.x + be[1] * wa.y + be[2] * wa.z + be[3] * wa.w
              + be[4] * wb.x + be[5] * wb.y + be[6] * wb.z + be[7] * wb.w;
    }
    __syncthreads();

    int d = pairs[nb * 3], e1 = pairs[nb * 3 + 1], e2 = pairs[nb * 3 + 2];
    size_t base = (((size_t)d * ENT_ + e1) * ENT_ + e2) * OUT_;
    for (int o = tid; o < OUT_; o += blockDim.x) {
        float acc = fcb[o];
        for (int k = 0; k < H2_; k++) acc += sv[k] * fcW[(size_t)o * H2_ + k];
        out[base + o] = acc;
    }
}

extern "C" void kernel_launch(void* const* d_in, const int* in_sizes, int n_in,
                              void* d_out, int out_size) {
    const float* bag   = (const float*)d_in[0];
    const float* Wihf  = (const float*)d_in[1];
    const float* Whhf  = (const float*)d_in[2];
    const float* bihf  = (const float*)d_in[3];
    const float* bhhf  = (const float*)d_in[4];
    const float* Wihr  = (const float*)d_in[5];
    const float* Whhr  = (const float*)d_in[6];
    const float* bihr  = (const float*)d_in[7];
    const float* bhhr  = (const float*)d_in[8];
    const float* Wword = (const float*)d_in[9];
    const float* bword = (const float*)d_in[10];
    const float* pword = (const float*)d_in[11];
    const float* Wsent = (const float*)d_in[12];
    const float* bsent = (const float*)d_in[13];
    const float* psent = (const float*)d_in[14];
    const float* fcW   = (const float*)d_in[15];
    const float* fcb   = (const float*)d_in[16];
    const int*   pairs = (const int*)d_in[17];
    float* out = (float*)d_out;

    float *d_outT, *d_wvT, *d_sc, *d_sc2;
    cudaGetSymbolAddress((void**)&d_outT, g_outT);
    cudaGetSymbolAddress((void**)&d_wvT,  g_wvT);
    cudaGetSymbolAddress((void**)&d_sc,   g_score);
    cudaGetSymbolAddress((void**)&d_sc2,  g_score2);

    zero_prep_kernel<<<2048, 256>>>(out, out_size);
    transpose_w_kernel<<<512, 256>>>(Whhf, Whhr, Wihf, Wihr);
    transpose_bag_kernel<<<dim3(M_ / 32, 12), 256>>>(bag);
    input_proj_kernel<<<dim3(11, 2048, 2), 256>>>(bihf, bihr);
    for (int s = 0; s < T_; s++)
        gru_step_kernel<<<dim3(8, 32, 2), 256>>>(s, bhhf, bhhr);
    attn_score_kernel<<<M_ / 128, 256>>>(d_outT, (size_t)M_, Wword, bword, pword, d_sc);
    word_vec_kernel<<<dim3(B_ / 128, 8), 128>>>();
    attn_score_kernel<<<B_ / 128, 256>>>(d_wvT, (size_t)B_, Wsent, bsent, psent, d_sc2);
    sent_fc_scatter_kernel<<<NB_, 128>>>(pairs, fcW, fcb, out);
}

// round 15
// speedup vs baseline: 2.0780x; 1.1779x over previous
#include <cuda_runtime.h>
#include <math.h>

#define NB_ 512
#define MS_ 8
#define T_  64
#define IN_ 360
#define H_  230
#define H2_ 460
#define H3_ 690
#define OUT_ 53
#define ENT_ 8
#define B_  4096
#define M_  (B_ * T_)
#define KIP_ 368
#define KGR_ 240
#define KAT_ 464
#define WTC_ 768
#define WIC_ 704

typedef unsigned long long u64;

__device__ float g_xg[(size_t)2 * M_ * H3_];
__device__ float g_bagT[(size_t)KIP_ * M_];
__device__ float g_outT[(size_t)KAT_ * M_];
__device__ float g_hT[2 * 2 * KGR_ * B_];
__device__ float g_Wt[2 * KGR_ * WTC_];
__device__ float g_WihT[2 * KIP_ * WIC_];
__device__ float g_wvT[KAT_ * B_];
__device__ float g_score[M_];
__device__ float g_score2[B_];

__device__ __forceinline__ u64 pack_dup(float b) {
    u64 r; asm("mov.b64 %0, {%1, %2};" : "=l"(r) : "f"(b), "f"(b)); return r;
}
__device__ __forceinline__ void fma2(u64& acc, u64 a, u64 b) {
    asm("fma.rn.f32x2 %0, %1, %2, %0;" : "+l"(acc) : "l"(a), "l"(b));
}
__device__ __forceinline__ float2 unpk(u64 v) {
    float lo, hi; asm("mov.b64 {%0, %1}, %2;" : "=f"(lo), "=f"(hi) : "l"(v));
    return make_float2(lo, hi);
}
__device__ __forceinline__ float sigm(float x) { return 1.0f / (1.0f + __expf(-x)); }
__device__ __forceinline__ float tanh_f(float x) { return 1.0f - 2.0f / (1.0f + __expf(2.0f * x)); }
__device__ __forceinline__ float tf32r(float x) {
    unsigned u;
    asm("cvt.rna.tf32.f32 %0, %1;" : "=r"(u) : "f"(x));
    return __uint_as_float(u);
}
__device__ __forceinline__ unsigned tf32u(float x) {
    unsigned u;
    asm("cvt.rna.tf32.f32 %0, %1;" : "=r"(u) : "f"(x));
    return u;
}
__device__ __forceinline__ void cp16(void* d, const void* s) {
    unsigned sa = (unsigned)__cvta_generic_to_shared(d);
    asm volatile("cp.async.cg.shared.global [%0], [%1], 16;" :: "r"(sa), "l"(s));
}
__device__ __forceinline__ void cp16z(void* d, const void* s, int bytes) {
    unsigned sa = (unsigned)__cvta_generic_to_shared(d);
    asm volatile("cp.async.cg.shared.global [%0], [%1], 16, %2;" :: "r"(sa), "l"(s), "r"(bytes));
}
#define CP_COMMIT() asm volatile("cp.async.commit_group;")
#define CP_WAIT1()  asm volatile("cp.async.wait_group 1;")

__global__ void zero_prep_kernel(float* out, int n_out) {
    size_t st = (size_t)gridDim.x * blockDim.x;
    size_t i0 = (size_t)blockIdx.x * blockDim.x + threadIdx.x;
    for (size_t i = i0; i < (size_t)n_out; i += st) out[i] = 0.f;
    for (size_t i = i0; i < (size_t)2 * 2 * KGR_ * B_; i += st) g_hT[i] = 0.f;
    for (size_t i = i0; i < (size_t)(KIP_ - IN_) * M_; i += st) g_bagT[(size_t)IN_ * M_ + i] = 0.f;
    for (size_t i = i0; i < (size_t)(KAT_ - H2_) * M_; i += st) g_outT[(size_t)H2_ * M_ + i] = 0.f;
    for (size_t i = i0; i < (size_t)(KAT_ - H2_) * B_; i += st) g_wvT[(size_t)H2_ * B_ + i] = 0.f;
}

__global__ void transpose_w_kernel(const float* __restrict__ Whhf, const float* __restrict__ Whhr,
                                   const float* __restrict__ Wihf, const float* __restrict__ Wihr) {
    size_t st = (size_t)gridDim.x * blockDim.x;
    size_t i0 = (size_t)blockIdx.x * blockDim.x + threadIdx.x;
    for (size_t i = i0; i < (size_t)2 * KGR_ * WTC_; i += st) {
        int dir = (int)(i / (KGR_ * WTC_)), rem = (int)(i % (KGR_ * WTC_));
        int k = rem / WTC_, j = rem % WTC_, g = j >> 8, c = j & 255;
        const float* Wh = dir ? Whhr : Whhf;
        g_Wt[i] = (k < H_ && c < H_) ? Wh[(size_t)(g * H_ + c) * H_ + k] : 0.f;
    }
    for (size_t i = i0; i < (size_t)2 * KIP_ * WIC_; i += st) {
        int dir = (int)(i / (KIP_ * WIC_)), rem = (int)(i % (KIP_ * WIC_));
        int k = rem / WIC_, n = rem % WIC_;
        const float* Wi = dir ? Wihr : Wihf;
        g_WihT[i] = (k < IN_ && n < H3_) ? tf32r(Wi[(size_t)n * IN_ + k]) : 0.f;
    }
}

__global__ __launch_bounds__(256) void transpose_bag_kernel(const float* __restrict__ bag) {
    __shared__ float tile[32][33];
    int m0 = blockIdx.x * 32, k0 = blockIdx.y * 32;
    int cIn = threadIdx.x & 31, rIn = threadIdx.x >> 5;
#pragma unroll
    for (int rr = 0; rr < 4; rr++) {
        int r = rIn + rr * 8, gk = k0 + cIn;
        tile[r][cIn] = (gk < IN_) ? bag[(size_t)(m0 + r) * IN_ + gk] : 0.f;
    }
    __syncthreads();
#pragma unroll
    for (int rr = 0; rr < 4; rr++) {
        int r = rIn + rr * 8, gk = k0 + r;
        if (gk < IN_) g_bagT[(size_t)gk * M_ + m0 + cIn] = tf32r(tile[cIn][r]);
    }
}

// ---- input projection via TF32 mma.sync ----
__global__ __launch_bounds__(256, 3) void input_proj_kernel(
    const float* __restrict__ bf, const float* __restrict__ br)
{
    const int dir = blockIdx.z;
    const float* __restrict__ bias = dir ? br : bf;
    float* __restrict__ xg = g_xg + (size_t)dir * M_ * H3_;
    const int n0 = blockIdx.x * 64;
    const size_t m0 = (size_t)blockIdx.y * 128;

    __shared__ __align__(16) float smA[3][16][136];
    __shared__ __align__(16) float smB[3][16][72];

    const int tid = threadIdx.x;
    const int lane = tid & 31, warp = tid >> 5;
    const int wm = (warp & 3) * 32, wn = (warp >> 2) * 32;
    const int lq = lane & 3, rq = lane >> 2;

    const int aK0 = tid >> 5, aM4 = (tid & 31) * 4, aK1 = aK0 + 8;
    const int bK = tid >> 4, bN4 = (tid & 15) * 4;
    const float* aS0 = g_bagT + (size_t)aK0 * M_ + m0 + aM4;
    const float* aS1 = g_bagT + (size_t)aK1 * M_ + m0 + aM4;
    const float* bS  = g_WihT + (size_t)dir * KIP_ * WIC_ + (size_t)bK * WIC_ + n0 + bN4;

    float acc[2][4][4];
#pragma unroll
    for (int i = 0; i < 2; i++)
#pragma unroll
        for (int j = 0; j < 4; j++)
#pragma unroll
            for (int q = 0; q < 4; q++) acc[i][j][q] = 0.f;

    const int NST = KIP_ / 16;  // 23
#pragma unroll
    for (int st = 0; st < 2; st++) {
        cp16(&smA[st][aK0][aM4], aS0); aS0 += (size_t)16 * M_;
        cp16(&smA[st][aK1][aM4], aS1); aS1 += (size_t)16 * M_;
        cp16(&smB[st][bK][bN4], bS);   bS  += (size_t)16 * WIC_;
        CP_COMMIT();
    }
    for (int it = 0; it < NST; it++) {
        CP_WAIT1();
        __syncthreads();
        if (it + 2 < NST) {
            const int st = (it + 2) % 3;
            cp16(&smA[st][aK0][aM4], aS0); aS0 += (size_t)16 * M_;
            cp16(&smA[st][aK1][aM4], aS1); aS1 += (size_t)16 * M_;
            cp16(&smB[st][bK][bN4], bS);   bS  += (size_t)16 * WIC_;
        }
        CP_COMMIT();
        const int cur = it % 3;
#pragma unroll
        for (int k8 = 0; k8 < 16; k8 += 8) {
            const int kr = k8 + lq;
            unsigned af[2][4], bfr[4][2];
#pragma unroll
            for (int i = 0; i < 2; i++) {
                int rm = wm + i * 16 + rq;
                af[i][0] = __float_as_uint(smA[cur][kr][rm]);
                af[i][1] = __float_as_uint(smA[cur][kr][rm + 8]);
                af[i][2] = __float_as_uint(smA[cur][kr + 4][rm]);
                af[i][3] = __float_as_uint(smA[cur][kr + 4][rm + 8]);
            }
#pragma unroll
            for (int j = 0; j < 4; j++) {
                int nb = wn + j * 8 + rq;
                bfr[j][0] = __float_as_uint(smB[cur][kr][nb]);
                bfr[j][1] = __float_as_uint(smB[cur][kr + 4][nb]);
            }
#pragma unroll
            for (int i = 0; i < 2; i++)
#pragma unroll
                for (int j = 0; j < 4; j++)
                    asm("mma.sync.aligned.m16n8k8.row.col.f32.tf32.tf32.f32 "
                        "{%0,%1,%2,%3}, {%4,%5,%6,%7}, {%8,%9}, {%0,%1,%2,%3};"
                        : "+f"(acc[i][j][0]), "+f"(acc[i][j][1]),
                          "+f"(acc[i][j][2]), "+f"(acc[i][j][3])
                        : "r"(af[i][0]), "r"(af[i][1]), "r"(af[i][2]), "r"(af[i][3]),
                          "r"(bfr[j][0]), "r"(bfr[j][1]));
        }
    }

#pragma unroll
    for (int j = 0; j < 4; j++) {
        int n = n0 + wn + j * 8 + lq * 2;
        if (n >= H3_) continue;
        float b0v = bias[n], b1v = bias[n + 1];
#pragma unroll
        for (int i = 0; i < 2; i++) {
            int mmb = (int)m0 + wm + i * 16 + rq;
#pragma unroll
            for (int rr = 0; rr < 2; rr++) {
                int mm = mmb + rr * 8;               // mm = b*T + t
                size_t row = ((size_t)(mm & 63) * B_ + (size_t)(mm >> 6)) * H3_;
                *(float2*)&xg[row + n] =
                    make_float2(acc[i][j][rr * 2] + b0v, acc[i][j][rr * 2 + 1] + b1v);
            }
        }
    }
}

// ---- GRU step: gates = hT^T @ WhhT, fused nonlinearity (f32x2) ----
__global__ __launch_bounds__(256, 3) void gru_step_kernel(int s,
    const float* __restrict__ bhf, const float* __restrict__ bhr)
{
    const int dir = blockIdx.z;
    const int tIdx = dir ? (T_ - 1 - s) : s;
    const float* __restrict__ bhh = dir ? bhr : bhf;
    const float* __restrict__ hTprev = g_hT + ((size_t)dir * 2 + (s & 1)) * KGR_ * B_;
    float*       __restrict__ hTnext = g_hT + ((size_t)dir * 2 + ((s + 1) & 1)) * KGR_ * B_;
    const float* __restrict__ xg = g_xg + (size_t)dir * M_ * H3_;
    const float* __restrict__ Wtd = g_Wt + (size_t)dir * KGR_ * WTC_;
    const int c0 = blockIdx.x * 32;
    const size_t m0 = (size_t)blockIdx.y * 128;

    __shared__ __align__(16) float smA[3 * 16 * 128];
    __shared__ __align__(16) float smB[3 * 16 * 96];
#define GRA(st,k,r)   smA[((st)*16+(k))*128+(r)]
#define GRB(st,k,g,c) smB[(((st)*16+(k))*3+(g))*32+(c)]
    const int tid = threadIdx.x, tx = tid & 15, ty = tid >> 4;
    const int aK0 = tid >> 5, aM = (tid & 31) * 4, aK1 = aK0 + 8;
    const float* aS0 = hTprev + (size_t)aK0 * B_ + m0 + aM;
    const float* aS1 = hTprev + (size_t)aK1 * B_ + m0 + aM;
    const int id1 = 256 + tid;
    const int bK0 = tid / 24, bJ0 = tid % 24, bK1 = id1 / 24, bJ1 = id1 % 24;
    const int bG0 = bJ0 >> 3, bC0 = (bJ0 & 7) * 4, bG1 = bJ1 >> 3, bC1 = (bJ1 & 7) * 4;
    const float* bS0 = Wtd + (size_t)bK0 * WTC_ + bG0 * 256 + c0 + bC0;
    const float* bS1 = Wtd + (size_t)bK1 * WTC_ + bG1 * 256 + c0 + bC1;
    const bool b1ok = tid < 128;

    u64 acc[4][6];
#pragma unroll
    for (int i = 0; i < 4; i++)
#pragma unroll
        for (int j = 0; j < 6; j++) acc[i][j] = 0ull;

    const int NST = KGR_ / 16;  // 15
#pragma unroll
    for (int st = 0; st < 2; st++) {
        cp16(&GRA(st, aK0, aM), aS0); aS0 += (size_t)16 * B_;
        cp16(&GRA(st, aK1, aM), aS1); aS1 += (size_t)16 * B_;
        cp16(&GRB(st, bK0, bG0, bC0), bS0); bS0 += (size_t)16 * WTC_;
        if (b1ok) { cp16(&GRB(st, bK1, bG1, bC1), bS1); bS1 += (size_t)16 * WTC_; }
        CP_COMMIT();
    }
    for (int it = 0; it < NST; it++) {
        CP_WAIT1();
        __syncthreads();
        if (it + 2 < NST) {
            const int st = (it + 2) % 3;
            cp16(&GRA(st, aK0, aM), aS0); aS0 += (size_t)16 * B_;
            cp16(&GRA(st, aK1, aM), aS1); aS1 += (size_t)16 * B_;
            cp16(&GRB(st, bK0, bG0, bC0), bS0); bS0 += (size_t)16 * WTC_;
            if (b1ok) { cp16(&GRB(st, bK1, bG1, bC1), bS1); bS1 += (size_t)16 * WTC_; }
        }
        CP_COMMIT();
        const int cur = it % 3;
#pragma unroll
        for (int k = 0; k < 16; k++) {
            ulonglong2 A0 = *(const ulonglong2*)&GRA(cur, k, ty * 8);
            ulonglong2 A1 = *(const ulonglong2*)&GRA(cur, k, ty * 8 + 4);
            u64 a[4] = {A0.x, A0.y, A1.x, A1.y};
#pragma unroll
            for (int g = 0; g < 3; g++) {
                float2 w2 = *(const float2*)&GRB(cur, k, g, tx * 2);
                u64 b0 = pack_dup(w2.x);
                u64 b1 = pack_dup(w2.y);
#pragma unroll
                for (int i = 0; i < 4; i++) fma2(acc[i][g * 2],     a[i], b0);
#pragma unroll
                for (int i = 0; i < 4; i++) fma2(acc[i][g * 2 + 1], a[i], b1);
            }
        }
    }

    const int c = c0 + tx * 2;
    if (c >= H_) return;
    const float br0 = bhh[c],          br1 = bhh[c + 1];
    const float bz0 = bhh[H_ + c],     bz1 = bhh[H_ + c + 1];
    const float bq0 = bhh[2 * H_ + c], bq1 = bhh[2 * H_ + c + 1];

    float hp0[8], hp1[8], hv0[8], hv1[8];
    {
        const float* h0p = hTprev + (size_t)c * B_ + m0 + ty * 8;
        const float* h1p = hTprev + (size_t)(c + 1) * B_ + m0 + ty * 8;
        *(float4*)&hp0[0] = *(const float4*)h0p;
        *(float4*)&hp0[4] = *(const float4*)(h0p + 4);
        *(float4*)&hp1[0] = *(const float4*)h1p;
        *(float4*)&hp1[4] = *(const float4*)(h1p + 4);
    }
#pragma unroll
    for (int i = 0; i < 4; i++) {
        float2 vr0 = unpk(acc[i][0]), vr1 = unpk(acc[i][1]);
        float2 vz0 = unpk(acc[i][2]), vz1 = unpk(acc[i][3]);
        float2 vq0 = unpk(acc[i][4]), vq1 = unpk(acc[i][5]);
#pragma unroll
        for (int half = 0; half < 2; half++) {
            int j = i * 2 + half;
            size_t b = m0 + ty * 8 + j;
            size_t xbase = ((size_t)tIdx * B_ + b) * H3_;
            float2 axr = *(const float2*)&xg[xbase + c];
            float2 axz = *(const float2*)&xg[xbase + H_ + c];
            float2 axn = *(const float2*)&xg[xbase + 2 * H_ + c];
            float ar0 = half ? vr0.y : vr0.x, ar1 = half ? vr1.y : vr1.x;
            float az0 = half ? vz0.y : vz0.x, az1 = half ? vz1.y : vz1.x;
            float aq0 = half ? vq0.y : vq0.x, aq1 = half ? vq1.y : vq1.x;
            float r0 = sigm(axr.x + ar0 + br0);
            float r1 = sigm(axr.y + ar1 + br1);
            float z0 = sigm(axz.x + az0 + bz0);
            float z1 = sigm(axz.y + az1 + bz1);
            float q0 = tanh_f(axn.x + r0 * (aq0 + bq0));
            float q1 = tanh_f(axn.y + r1 * (aq1 + bq1));
            hv0[j] = (1.f - z0) * q0 + z0 * hp0[j];
            hv1[j] = (1.f - z1) * q1 + z1 * hp1[j];
        }
    }
    float* hn0 = hTnext + (size_t)c * B_ + m0 + ty * 8;
    float* hn1 = hTnext + (size_t)(c + 1) * B_ + m0 + ty * 8;
    *(float4*)hn0       = make_float4(hv0[0], hv0[1], hv0[2], hv0[3]);
    *(float4*)(hn0 + 4) = make_float4(hv0[4], hv0[5], hv0[6], hv0[7]);
    *(float4*)hn1       = make_float4(hv1[0], hv1[1], hv1[2], hv1[3]);
    *(float4*)(hn1 + 4) = make_float4(hv1[4], hv1[5], hv1[6], hv1[7]);

    // g_outT gets tf32-rounded values (consumed by TF32 attention MMA)
    size_t ocol = (size_t)tIdx * B_ + m0 + ty * 8;
    float* ot0 = g_outT + (size_t)(dir * H_ + c) * M_ + ocol;
    float* ot1 = g_outT + (size_t)(dir * H_ + c + 1) * M_ + ocol;
    *(float4*)ot0       = make_float4(tf32r(hv0[0]), tf32r(hv0[1]), tf32r(hv0[2]), tf32r(hv0[3]));
    *(float4*)(ot0 + 4) = make_float4(tf32r(hv0[4]), tf32r(hv0[5]), tf32r(hv0[6]), tf32r(hv0[7]));
    *(float4*)ot1       = make_float4(tf32r(hv1[0]), tf32r(hv1[1]), tf32r(hv1[2]), tf32r(hv1[3]));
    *(float4*)(ot1 + 4) = make_float4(tf32r(hv1[4]), tf32r(hv1[5]), tf32r(hv1[6]), tf32r(hv1[7]));
#undef GRA
#undef GRB
}

// ---- fused attention score via TF32 mma.sync ----
// score[m] = sum_n tanh((A@W)[m,n]+b[n])*p[n]; A k-major [KAT_][ldA] (tf32-rounded)
__global__ __launch_bounds__(256, 3) void attn_score_kernel(
    const float* __restrict__ A, size_t ldA,
    const float* __restrict__ W, const float* __restrict__ bias,
    const float* __restrict__ proj, float* __restrict__ score)
{
    const size_t m0 = (size_t)blockIdx.x * 128;
    __shared__ __align__(16) float smA[3][16][136];
    __shared__ __align__(16) float smB[3][16][72];
    __shared__ float red[128][8];

    const int tid = threadIdx.x;
    const int lane = tid & 31, warp = tid >> 5;
    const int wm = (warp & 3) * 32, wn = (warp >> 2) * 32;
    const int lq = lane & 3, rq = lane >> 2;

    const int aK0 = tid >> 5, aM4 = (tid & 31) * 4, aK1 = aK0 + 8;
    const int bK = tid >> 4, bN4 = (tid & 15) * 4;
    const float* aB0 = A + (size_t)aK0 * ldA + m0 + aM4;
    const float* aB1 = A + (size_t)aK1 * ldA + m0 + aM4;

    float sp[4] = {0.f, 0.f, 0.f, 0.f};
    const int NST = KAT_ / 16;  // 29

    for (int n0 = 0; n0 < H2_; n0 += 64) {
        float acc[2][4][4];
#pragma unroll
        for (int i = 0; i < 2; i++)
#pragma unroll
            for (int j = 0; j < 4; j++)
#pragma unroll
                for (int q = 0; q < 4; q++) acc[i][j][q] = 0.f;

        int rem = H2_ - (n0 + bN4);
        int nbytes = rem >= 4 ? 16 : 0;
        const float* aS0 = aB0;
        const float* aS1 = aB1;

        __syncthreads();
#pragma unroll
        for (int st = 0; st < 2; st++) {
            cp16(&smA[st][aK0][aM4], aS0); aS0 += (size_t)16 * ldA;
            cp16(&smA[st][aK1][aM4], aS1); aS1 += (size_t)16 * ldA;
            int kk = st * 16 + bK;
            int bytes = (kk < H2_) ? nbytes : 0;
            const float* src = bytes ? (W + (size_t)kk * H2_ + n0 + bN4) : W;
            cp16z(&smB[st][bK][bN4], src, bytes);
            CP_COMMIT();
        }
        for (int it = 0; it < NST; it++) {
            CP_WAIT1();
            __syncthreads();
            if (it + 2 < NST) {
                const int st = (it + 2) % 3;
                cp16(&smA[st][aK0][aM4], aS0); aS0 += (size_t)16 * ldA;
                cp16(&smA[st][aK1][aM4], aS1); aS1 += (size_t)16 * ldA;
                int kk = (it + 2) * 16 + bK;
                int bytes = (kk < H2_) ? nbytes : 0;
                const float* src = bytes ? (W + (size_t)kk * H2_ + n0 + bN4) : W;
                cp16z(&smB[st][bK][bN4], src, bytes);
            }
            CP_COMMIT();
            const int cur = it % 3;
#pragma unroll
            for (int k8 = 0; k8 < 16; k8 += 8) {
                const int kr = k8 + lq;
                unsigned af[2][4], bfr[4][2];
#pragma unroll
                for (int i = 0; i < 2; i++) {
                    int rm = wm + i * 16 + rq;
                    af[i][0] = __float_as_uint(smA[cur][kr][rm]);
                    af[i][1] = __float_as_uint(smA[cur][kr][rm + 8]);
                    af[i][2] = __float_as_uint(smA[cur][kr + 4][rm]);
                    af[i][3] = __float_as_uint(smA[cur][kr + 4][rm + 8]);
                }
#pragma unroll
                for (int j = 0; j < 4; j++) {
                    int nb = wn + j * 8 + rq;
                    bfr[j][0] = tf32u(smB[cur][kr][nb]);       // W raw -> tf32
                    bfr[j][1] = tf32u(smB[cur][kr + 4][nb]);
                }
#pragma unroll
                for (int i = 0; i < 2; i++)
#pragma unroll
                    for (int j = 0; j < 4; j++)
                        asm("mma.sync.aligned.m16n8k8.row.col.f32.tf32.tf32.f32 "
                            "{%0,%1,%2,%3}, {%4,%5,%6,%7}, {%8,%9}, {%0,%1,%2,%3};"
                            : "+f"(acc[i][j][0]), "+f"(acc[i][j][1]),
                              "+f"(acc[i][j][2]), "+f"(acc[i][j][3])
                            : "r"(af[i][0]), "r"(af[i][1]), "r"(af[i][2]), "r"(af[i][3]),
                              "r"(bfr[j][0]), "r"(bfr[j][1]));
            }
        }
        // partial tanh-proj reduction for this n-slab
#pragma unroll
        for (int j = 0; j < 4; j++) {
            int n = n0 + wn + j * 8 + lq * 2;
            if (n >= H2_) continue;                 // pairs never straddle (H2 even)
            float bi0 = bias[n], bi1 = bias[n + 1];
            float pj0 = proj[n], pj1 = proj[n + 1];
#pragma unroll
            for (int i = 0; i < 2; i++)
#pragma unroll
                for (int rr = 0; rr < 2; rr++)
                    sp[i * 2 + rr] += tanh_f(acc[i][j][rr * 2] + bi0) * pj0
                                    + tanh_f(acc[i][j][rr * 2 + 1] + bi1) * pj1;
        }
    }
    __syncthreads();
#pragma unroll
    for (int i = 0; i < 2; i++)
#pragma unroll
        for (int rr = 0; rr < 2; rr++)
            red[wm + i * 16 + rr * 8 + rq][(warp >> 2) * 4 + lq] = sp[i * 2 + rr];
    __syncthreads();
    if (tid < 128) {
        float s = 0.f;
#pragma unroll
        for (int j = 0; j < 8; j++) s += red[tid][j];
        score[m0 + tid] = s;
    }
}

// ---- word softmax over t + weighted sum -> g_wvT[h][b] (tf32-rounded) ----
__global__ __launch_bounds__(128) void word_vec_kernel() {
    const int tid = threadIdx.x;
    const int b = blockIdx.x * 128 + tid;
    const int h0 = blockIdx.y * 58;
    const int hend = min(h0 + 58, H2_);
    __shared__ float al[T_][128];

    float mx = -1e30f;
#pragma unroll 8
    for (int t = 0; t < T_; t++) {
        float s = g_score[(size_t)t * B_ + b];
        al[t][tid] = s;
        mx = fmaxf(mx, s);
    }
    float sm = 0.f;
#pragma unroll 8
    for (int t = 0; t < T_; t++) sm += __expf(al[t][tid] - mx);
    float inv = 1.0f / sm;
#pragma unroll 8
    for (int t = 0; t < T_; t++) al[t][tid] = __expf(al[t][tid] - mx) * inv;

    for (int h = h0; h < hend; h++) {
        const float* row = g_outT + (size_t)h * M_ + b;
        float acc = 0.f;
#pragma unroll 8
        for (int t = 0; t < T_; t++) acc += al[t][tid] * row[(size_t)t * B_];
        g_wvT[(size_t)h * B_ + b] = tf32r(acc);
    }
}

// ---- sentence softmax + sent_vec + FC + scatter ----
__global__ __launch_bounds__(128) void sent_fc_scatter_kernel(
    const int* __restrict__ pairs, const float* __restrict__ fcW,
    const float* __restrict__ fcb, float* __restrict__ out)
{
    int nb = blockIdx.x;
    int tid = threadIdx.x;
    __shared__ float sv[H2_];

    float sc[MS_], mx = -1e30f;
#pragma unroll
    for (int s = 0; s < MS_; s++) { sc[s] = g_score2[nb * MS_ + s]; mx = fmaxf(mx, sc[s]); }
    float sm = 0.f;
#pragma unroll
    for (int s = 0; s < MS_; s++) sm += __expf(sc[s] - mx);
    float be[MS_];
#pragma unroll
    for (int s = 0; s < MS_; s++) be[s] = __expf(sc[s] - mx) / sm;

    for (int h = tid; h < H2_; h += blockDim.x) {
        const float* wp = g_wvT + (size_t)h * B_ + nb * MS_;
        float4 wa = *(const float4*)wp;
        float4 wb = *(const float4*)(wp + 4);
        sv[h] = be[0] * wa.x + be[1] * wa.y + be[2] * wa.z + be[3] * wa.w
              + be[4] * wb.x + be[5] * wb.y + be[6] * wb.z + be[7] * wb.w;
    }
    __syncthreads();

    int d = pairs[nb * 3], e1 = pairs[nb * 3 + 1], e2 = pairs[nb * 3 + 2];
    size_t base = (((size_t)d * ENT_ + e1) * ENT_ + e2) * OUT_;
    for (int o = tid; o < OUT_; o += blockDim.x) {
        float acc = fcb[o];
        for (int k = 0; k < H2_; k++) acc += sv[k] * fcW[(size_t)o * H2_ + k];
        out[base + o] = acc;
    }
}

extern "C" void kernel_launch(void* const* d_in, const int* in_sizes, int n_in,
                              void* d_out, int out_size) {
    const float* bag   = (const float*)d_in[0];
    const float* Wihf  = (const float*)d_in[1];
    const float* Whhf  = (const float*)d_in[2];
    const float* bihf  = (const float*)d_in[3];
    const float* bhhf  = (const float*)d_in[4];
    const float* Wihr  = (const float*)d_in[5];
    const float* Whhr  = (const float*)d_in[6];
    const float* bihr  = (const float*)d_in[7];
    const float* bhhr  = (const float*)d_in[8];
    const float* Wword = (const float*)d_in[9];
    const float* bword = (const float*)d_in[10];
    const float* pword = (const float*)d_in[11];
    const float* Wsent = (const float*)d_in[12];
    const float* bsent = (const float*)d_in[13];
    const float* psent = (const float*)d_in[14];
    const float* fcW   = (const float*)d_in[15];
    const float* fcb   = (const float*)d_in[16];
    const int*   pairs = (const int*)d_in[17];
    float* out = (float*)d_out;

    float *d_outT, *d_wvT, *d_sc, *d_sc2;
    cudaGetSymbolAddress((void**)&d_outT, g_outT);
    cudaGetSymbolAddress((void**)&d_wvT,  g_wvT);
    cudaGetSymbolAddress((void**)&d_sc,   g_score);
    cudaGetSymbolAddress((void**)&d_sc2,  g_score2);

    zero_prep_kernel<<<2048, 256>>>(out, out_size);
    transpose_w_kernel<<<512, 256>>>(Whhf, Whhr, Wihf, Wihr);
    transpose_bag_kernel<<<dim3(M_ / 32, 12), 256>>>(bag);
    input_proj_kernel<<<dim3(11, 2048, 2), 256>>>(bihf, bihr);
    for (int s = 0; s < T_; s++)
        gru_step_kernel<<<dim3(8, 32, 2), 256>>>(s, bhhf, bhhr);
    attn_score_kernel<<<M_ / 128, 256>>>(d_outT, (size_t)M_, Wword, bword, pword, d_sc);
    word_vec_kernel<<<dim3(B_ / 128, 8), 128>>>();
    attn_score_kernel<<<B_ / 128, 256>>>(d_wvT, (size_t)B_, Wsent, bsent, psent, d_sc2);
    sent_fc_scatter_kernel<<<NB_, 128>>>(pairs, fcW, fcb, out);
}